// round 1
// baseline (speedup 1.0000x reference)
#include <cuda_runtime.h>
#include <math.h>

#define BB 4
#define TT_SEQ 4096
#define DD 1024
#define HD 64
#define NTOK (BB*TT_SEQ)

// Scratch for projected Q (pre-scaled by hd^-0.5), K, V. [B*T, HD]
__device__ float g_Q[NTOK*HD];
__device__ float g_K[NTOK*HD];
__device__ float g_V[NTOK*HD];

// ---------------------------------------------------------------------------
// Kernel 1: fused QKV projection.
// Block = 256 threads handles 16 tokens. x tile staged in smem (64KB).
// Each of 8 warps computes 24 of the 192 output rows (Q/K/V x 64 heads dims),
// with coalesced float4 loads of W (L2-resident) and warp-shuffle reduction.
// ---------------------------------------------------------------------------
#define QKV_TT 16

__global__ __launch_bounds__(256) void qkv_kernel(
    const float* __restrict__ x,
    const float* __restrict__ Wq,
    const float* __restrict__ Wk,
    const float* __restrict__ Wv)
{
    __shared__ float xs[QKV_TT * DD];   // 64 KB
    const int tb = blockIdx.x * QKV_TT; // token base (flattened B*T)

    // cooperative coalesced load of x tile
    const float4* xg = (const float4*)(x + (size_t)tb * DD);
    float4* xs4 = (float4*)xs;
    #pragma unroll 4
    for (int i = threadIdx.x; i < QKV_TT * DD / 4; i += 256)
        xs4[i] = xg[i];
    __syncthreads();

    const int warp = threadIdx.x >> 5;
    const int lane = threadIdx.x & 31;

    for (int h = warp; h < 3 * HD; h += 8) {
        const int m  = h >> 6;   // 0=Q, 1=K, 2=V
        const int hh = h & 63;
        const float* Wrow = (m == 0 ? Wq : (m == 1 ? Wk : Wv)) + (size_t)hh * DD;
        const float4* Wrow4 = (const float4*)Wrow;

        float4 w4[8];
        #pragma unroll
        for (int i = 0; i < 8; i++) w4[i] = Wrow4[i * 32 + lane];  // coalesced

        float acc[QKV_TT];
        #pragma unroll
        for (int t = 0; t < QKV_TT; t++) acc[t] = 0.f;

        #pragma unroll
        for (int i = 0; i < 8; i++) {
            #pragma unroll
            for (int t = 0; t < QKV_TT; t++) {
                float4 xv = xs4[t * (DD / 4) + i * 32 + lane];
                acc[t] += w4[i].x * xv.x + w4[i].y * xv.y
                        + w4[i].z * xv.z + w4[i].w * xv.w;
            }
        }

        // warp-reduce each token's partial sum
        #pragma unroll
        for (int t = 0; t < QKV_TT; t++) {
            float v = acc[t];
            v += __shfl_xor_sync(0xffffffffu, v, 16);
            v += __shfl_xor_sync(0xffffffffu, v, 8);
            v += __shfl_xor_sync(0xffffffffu, v, 4);
            v += __shfl_xor_sync(0xffffffffu, v, 2);
            v += __shfl_xor_sync(0xffffffffu, v, 1);
            acc[t] = v;   // all lanes hold the full sum
        }

        if (lane < QKV_TT) {
            float val = 0.f;
            #pragma unroll
            for (int t = 0; t < QKV_TT; t++) if (lane == t) val = acc[t];
            if (m == 0) val *= 0.125f;   // fold hd^-0.5 = 1/8 into Q
            float* dst = (m == 0 ? g_Q : (m == 1 ? g_K : g_V));
            dst[(size_t)(tb + lane) * HD + hh] = val;
        }
    }
}

// ---------------------------------------------------------------------------
// Kernel 2: causal flash attention.
// Block = 128 threads, one thread per query (q + acc in registers).
// K/V tiles of 64 keys staged in smem. Online softmax with a branch on
// new-max so the common path per key is 64 score FMA + 64 acc FMA.
// Query tiles are processed heavy-first (reversed within each batch) to
// mitigate the causal work skew across the single wave.
// ---------------------------------------------------------------------------
#define QT 128
#define KT 64

__global__ __launch_bounds__(128) void attn_kernel(float* __restrict__ out)
{
    __shared__ float Ks[KT * HD];   // 16 KB
    __shared__ float Vs[KT * HD];   // 16 KB

    const int nTilesPerB = TT_SEQ / QT;                  // 32
    const int b    = blockIdx.x / nTilesPerB;
    const int tile = nTilesPerB - 1 - (blockIdx.x % nTilesPerB);  // heavy first
    const int q0   = tile * QT;
    const int qIdx = q0 + threadIdx.x;                   // query index in [0,T)

    const float* Qb = g_Q + (size_t)b * TT_SEQ * HD;
    const float* Kb = g_K + (size_t)b * TT_SEQ * HD;
    const float* Vb = g_V + (size_t)b * TT_SEQ * HD;

    // load this thread's query row (already scaled by 1/8)
    float q[HD];
    {
        const float4* qr = (const float4*)(Qb + (size_t)qIdx * HD);
        #pragma unroll
        for (int i = 0; i < 16; i++) {
            float4 v = qr[i];
            q[4*i+0] = v.x; q[4*i+1] = v.y; q[4*i+2] = v.z; q[4*i+3] = v.w;
        }
    }

    float acc[HD];
    #pragma unroll
    for (int i = 0; i < HD; i++) acc[i] = 0.f;
    float mval = -1e30f;
    float lsum = 0.f;

    const int kmax = q0 + QT;   // keys [0, kmax); multiple of KT

    for (int k0 = 0; k0 < kmax; k0 += KT) {
        __syncthreads();
        {   // cooperative coalesced K/V tile load
            const float4* kg = (const float4*)(Kb + (size_t)k0 * HD);
            const float4* vg = (const float4*)(Vb + (size_t)k0 * HD);
            float4* Ks4 = (float4*)Ks;
            float4* Vs4 = (float4*)Vs;
            #pragma unroll 4
            for (int i = threadIdx.x; i < KT * HD / 4; i += QT) {
                Ks4[i] = kg[i];
                Vs4[i] = vg[i];
            }
        }
        __syncthreads();

        for (int j = 0; j < KT; j++) {
            const int kk = k0 + j;
            const float4* kr = (const float4*)(Ks + j * HD);

            float s0 = 0.f, s1 = 0.f, s2 = 0.f, s3 = 0.f;
            #pragma unroll
            for (int i = 0; i < 16; i += 4) {
                float4 a = kr[i+0];
                s0 += a.x*q[4*(i+0)+0] + a.y*q[4*(i+0)+1] + a.z*q[4*(i+0)+2] + a.w*q[4*(i+0)+3];
                float4 bv = kr[i+1];
                s1 += bv.x*q[4*(i+1)+0] + bv.y*q[4*(i+1)+1] + bv.z*q[4*(i+1)+2] + bv.w*q[4*(i+1)+3];
                float4 c = kr[i+2];
                s2 += c.x*q[4*(i+2)+0] + c.y*q[4*(i+2)+1] + c.z*q[4*(i+2)+2] + c.w*q[4*(i+2)+3];
                float4 d = kr[i+3];
                s3 += d.x*q[4*(i+3)+0] + d.y*q[4*(i+3)+1] + d.z*q[4*(i+3)+2] + d.w*q[4*(i+3)+3];
            }
            float s = (s0 + s1) + (s2 + s3);
            s = (kk <= qIdx) ? s : -1e30f;   // causal mask

            const float4* vr = (const float4*)(Vs + j * HD);
            if (s > mval) {
                // new running max: rescale and add p=1 contribution
                float scale = __expf(mval - s);
                mval = s;
                lsum = lsum * scale + 1.f;
                #pragma unroll
                for (int i = 0; i < 16; i++) {
                    float4 v = vr[i];
                    acc[4*i+0] = acc[4*i+0] * scale + v.x;
                    acc[4*i+1] = acc[4*i+1] * scale + v.y;
                    acc[4*i+2] = acc[4*i+2] * scale + v.z;
                    acc[4*i+3] = acc[4*i+3] * scale + v.w;
                }
            } else {
                float p = __expf(s - mval);   // masked keys: p == 0
                lsum += p;
                #pragma unroll
                for (int i = 0; i < 16; i++) {
                    float4 v = vr[i];
                    acc[4*i+0] += p * v.x;
                    acc[4*i+1] += p * v.y;
                    acc[4*i+2] += p * v.z;
                    acc[4*i+3] += p * v.w;
                }
            }
        }
    }

    const float inv = 1.f / lsum;
    float4* og = (float4*)(out + ((size_t)b * TT_SEQ + qIdx) * HD);
    #pragma unroll
    for (int i = 0; i < 16; i++) {
        float4 v;
        v.x = acc[4*i+0] * inv;
        v.y = acc[4*i+1] * inv;
        v.z = acc[4*i+2] * inv;
        v.w = acc[4*i+3] * inv;
        og[i] = v;
    }
}

extern "C" void kernel_launch(void* const* d_in, const int* in_sizes, int n_in,
                              void* d_out, int out_size)
{
    const float* x  = (const float*)d_in[0];
    const float* Wq = (const float*)d_in[1];
    const float* Wk = (const float*)d_in[2];
    const float* Wv = (const float*)d_in[3];
    float* out = (float*)d_out;

    qkv_kernel<<<NTOK / QKV_TT, 256>>>(x, Wq, Wk, Wv);
    attn_kernel<<<(BB * TT_SEQ) / QT, QT>>>(out);
}

// round 2
// speedup vs baseline: 1.9425x; 1.9425x over previous
#include <cuda_runtime.h>
#include <math.h>

#define BB 4
#define TT_SEQ 4096
#define DD 1024
#define HD 64
#define NTOK (BB*TT_SEQ)

#define QT 128          // queries per tile (one thread per query)
#define KT 64           // keys staged in smem at a time
#define CK 256          // keys per split-K chunk
#define TILES (TT_SEQ/QT)      // 32
#define NCH_MAX (TT_SEQ/CK)    // 16

// Scratch for projected Q (pre-scaled by hd^-0.5), K, V. [B*T, HD]
__device__ float g_Q[NTOK*HD];
__device__ float g_K[NTOK*HD];
__device__ float g_V[NTOK*HD];

// Split-K partials: unnormalized acc + running (m, l) per (b, tile, chunk, query)
__device__ float g_pacc[BB*TILES*NCH_MAX*QT*HD];   // 64 MB
__device__ float g_pm  [BB*TILES*NCH_MAX*QT];
__device__ float g_pl  [BB*TILES*NCH_MAX*QT];

// ---------------------------------------------------------------------------
// Kernel 1: fused QKV projection (unchanged from R1).
// ---------------------------------------------------------------------------
#define QKV_TT 16

__global__ __launch_bounds__(256) void qkv_kernel(
    const float* __restrict__ x,
    const float* __restrict__ Wq,
    const float* __restrict__ Wk,
    const float* __restrict__ Wv)
{
    __shared__ float xs[QKV_TT * DD];   // 64 KB
    const int tb = blockIdx.x * QKV_TT;

    const float4* xg = (const float4*)(x + (size_t)tb * DD);
    float4* xs4 = (float4*)xs;
    #pragma unroll 4
    for (int i = threadIdx.x; i < QKV_TT * DD / 4; i += 256)
        xs4[i] = xg[i];
    __syncthreads();

    const int warp = threadIdx.x >> 5;
    const int lane = threadIdx.x & 31;

    for (int h = warp; h < 3 * HD; h += 8) {
        const int m  = h >> 6;
        const int hh = h & 63;
        const float* Wrow = (m == 0 ? Wq : (m == 1 ? Wk : Wv)) + (size_t)hh * DD;
        const float4* Wrow4 = (const float4*)Wrow;

        float4 w4[8];
        #pragma unroll
        for (int i = 0; i < 8; i++) w4[i] = Wrow4[i * 32 + lane];

        float acc[QKV_TT];
        #pragma unroll
        for (int t = 0; t < QKV_TT; t++) acc[t] = 0.f;

        #pragma unroll
        for (int i = 0; i < 8; i++) {
            #pragma unroll
            for (int t = 0; t < QKV_TT; t++) {
                float4 xv = xs4[t * (DD / 4) + i * 32 + lane];
                acc[t] += w4[i].x * xv.x + w4[i].y * xv.y
                        + w4[i].z * xv.z + w4[i].w * xv.w;
            }
        }

        #pragma unroll
        for (int t = 0; t < QKV_TT; t++) {
            float v = acc[t];
            v += __shfl_xor_sync(0xffffffffu, v, 16);
            v += __shfl_xor_sync(0xffffffffu, v, 8);
            v += __shfl_xor_sync(0xffffffffu, v, 4);
            v += __shfl_xor_sync(0xffffffffu, v, 2);
            v += __shfl_xor_sync(0xffffffffu, v, 1);
            acc[t] = v;
        }

        if (lane < QKV_TT) {
            float val = 0.f;
            #pragma unroll
            for (int t = 0; t < QKV_TT; t++) if (lane == t) val = acc[t];
            if (m == 0) val *= 0.125f;   // fold hd^-0.5 = 1/8 into Q
            float* dst = (m == 0 ? g_Q : (m == 1 ? g_K : g_V));
            dst[(size_t)(tb + lane) * HD + hh] = val;
        }
    }
}

// ---------------------------------------------------------------------------
// Kernel 2: split-K causal flash attention (partial pass).
// grid = (NCH_MAX, TILES, BB); CTAs with chunk >= nch(tile) exit immediately.
// Each active CTA: 128 threads, one query per thread, processes <=256 keys,
// writes unnormalized acc plus (m, l).
// ---------------------------------------------------------------------------
__global__ __launch_bounds__(128) void attn_chunk_kernel()
{
    __shared__ float Ks[KT * HD];   // 16 KB
    __shared__ float Vs[KT * HD];   // 16 KB

    const int chunk = blockIdx.x;
    const int tile  = blockIdx.y;
    const int b     = blockIdx.z;

    const int kmax = (tile + 1) * QT;            // causal key bound for tile
    const int nch  = (kmax + CK - 1) / CK;       // active chunks for this tile
    if (chunk >= nch) return;

    const int kstart = chunk * CK;
    const int kend   = min(kstart + CK, kmax);

    const int q0   = tile * QT;
    const int qIdx = q0 + threadIdx.x;

    const float* Qb = g_Q + (size_t)b * TT_SEQ * HD;
    const float* Kb = g_K + (size_t)b * TT_SEQ * HD;
    const float* Vb = g_V + (size_t)b * TT_SEQ * HD;

    float q[HD];
    {
        const float4* qr = (const float4*)(Qb + (size_t)qIdx * HD);
        #pragma unroll
        for (int i = 0; i < 16; i++) {
            float4 v = qr[i];
            q[4*i+0] = v.x; q[4*i+1] = v.y; q[4*i+2] = v.z; q[4*i+3] = v.w;
        }
    }

    float acc[HD];
    #pragma unroll
    for (int i = 0; i < HD; i++) acc[i] = 0.f;
    float mval = -1e30f;
    float lsum = 0.f;

    for (int k0 = kstart; k0 < kend; k0 += KT) {
        __syncthreads();
        {
            const float4* kg = (const float4*)(Kb + (size_t)k0 * HD);
            const float4* vg = (const float4*)(Vb + (size_t)k0 * HD);
            float4* Ks4 = (float4*)Ks;
            float4* Vs4 = (float4*)Vs;
            #pragma unroll 4
            for (int i = threadIdx.x; i < KT * HD / 4; i += QT) {
                Ks4[i] = kg[i];
                Vs4[i] = vg[i];
            }
        }
        __syncthreads();

        for (int j = 0; j < KT; j++) {
            const int kk = k0 + j;
            const float4* kr = (const float4*)(Ks + j * HD);

            float s0 = 0.f, s1 = 0.f, s2 = 0.f, s3 = 0.f;
            #pragma unroll
            for (int i = 0; i < 16; i += 4) {
                float4 a = kr[i+0];
                s0 += a.x*q[4*(i+0)+0] + a.y*q[4*(i+0)+1] + a.z*q[4*(i+0)+2] + a.w*q[4*(i+0)+3];
                float4 bv = kr[i+1];
                s1 += bv.x*q[4*(i+1)+0] + bv.y*q[4*(i+1)+1] + bv.z*q[4*(i+1)+2] + bv.w*q[4*(i+1)+3];
                float4 c = kr[i+2];
                s2 += c.x*q[4*(i+2)+0] + c.y*q[4*(i+2)+1] + c.z*q[4*(i+2)+2] + c.w*q[4*(i+2)+3];
                float4 d = kr[i+3];
                s3 += d.x*q[4*(i+3)+0] + d.y*q[4*(i+3)+1] + d.z*q[4*(i+3)+2] + d.w*q[4*(i+3)+3];
            }
            float s = (s0 + s1) + (s2 + s3);
            s = (kk <= qIdx) ? s : -1e30f;   // causal mask

            const float4* vr = (const float4*)(Vs + j * HD);
            if (s > mval) {
                float scale = __expf(mval - s);
                mval = s;
                lsum = lsum * scale + 1.f;
                #pragma unroll
                for (int i = 0; i < 16; i++) {
                    float4 v = vr[i];
                    acc[4*i+0] = acc[4*i+0] * scale + v.x;
                    acc[4*i+1] = acc[4*i+1] * scale + v.y;
                    acc[4*i+2] = acc[4*i+2] * scale + v.z;
                    acc[4*i+3] = acc[4*i+3] * scale + v.w;
                }
            } else {
                float p = __expf(s - mval);
                lsum += p;
                #pragma unroll
                for (int i = 0; i < 16; i++) {
                    float4 v = vr[i];
                    acc[4*i+0] += p * v.x;
                    acc[4*i+1] += p * v.y;
                    acc[4*i+2] += p * v.z;
                    acc[4*i+3] += p * v.w;
                }
            }
        }
    }

    // write partials (unnormalized)
    const size_t pidx = (((size_t)(b * TILES + tile) * NCH_MAX + chunk) * QT) + threadIdx.x;
    g_pm[pidx] = mval;
    g_pl[pidx] = lsum;
    float4* pa = (float4*)(g_pacc + pidx * HD);
    #pragma unroll
    for (int i = 0; i < 16; i++) {
        float4 v;
        v.x = acc[4*i+0]; v.y = acc[4*i+1]; v.z = acc[4*i+2]; v.w = acc[4*i+3];
        pa[i] = v;
    }
}

// ---------------------------------------------------------------------------
// Kernel 3: combine split-K partials.
// One thread per (query, head-dim) element. 256 threads/block, 4096 blocks.
// Fully coalesced reads of g_pacc.
// ---------------------------------------------------------------------------
__global__ __launch_bounds__(256) void combine_kernel(float* __restrict__ out)
{
    const int gid = blockIdx.x * 256 + threadIdx.x;   // [0, NTOK*HD)
    const int q   = gid >> 6;       // global query index
    const int d   = gid & 63;       // head dim

    const int b      = q / TT_SEQ;
    const int t_in_b = q % TT_SEQ;
    const int tile   = t_in_b / QT;
    const int qi     = t_in_b % QT;

    const int kmax = (tile + 1) * QT;
    const int nch  = (kmax + CK - 1) / CK;

    const size_t base = ((size_t)(b * TILES + tile) * NCH_MAX) * QT + qi;

    // pass 1: global max
    float mstar = -1e30f;
    for (int i = 0; i < nch; i++) {
        float mi = g_pm[base + (size_t)i * QT];
        mstar = fmaxf(mstar, mi);
    }

    // pass 2: merge
    float L = 0.f, val = 0.f;
    for (int i = 0; i < nch; i++) {
        const size_t pidx = base + (size_t)i * QT;
        float w = __expf(g_pm[pidx] - mstar);
        L   += g_pl[pidx] * w;
        val += g_pacc[pidx * HD + d] * w;
    }

    out[(size_t)q * HD + d] = val / L;
}

extern "C" void kernel_launch(void* const* d_in, const int* in_sizes, int n_in,
                              void* d_out, int out_size)
{
    const float* x  = (const float*)d_in[0];
    const float* Wq = (const float*)d_in[1];
    const float* Wk = (const float*)d_in[2];
    const float* Wv = (const float*)d_in[3];
    float* out = (float*)d_out;

    qkv_kernel<<<NTOK / QKV_TT, 256>>>(x, Wq, Wk, Wv);

    dim3 agrid(NCH_MAX, TILES, BB);
    attn_chunk_kernel<<<agrid, QT>>>();

    combine_kernel<<<(NTOK * HD) / 256, 256>>>(out);
}

// round 3
// speedup vs baseline: 2.8679x; 1.4764x over previous
#include <cuda_runtime.h>
#include <math.h>

#define BB 4
#define TT_SEQ 4096
#define DD 1024
#define HD 64
#define NTOK (BB*TT_SEQ)

#define QT 128          // queries per tile (one thread per query)
#define KT 64           // keys staged in smem at a time
#define CK 256          // keys per split-K chunk
#define TILES (TT_SEQ/QT)      // 32
#define NCH_MAX (TT_SEQ/CK)    // 16

// Scratch for projected Q (pre-scaled by hd^-0.5), K, V. [B*T, HD]
__device__ float g_Q[NTOK*HD];
__device__ float g_K[NTOK*HD];
__device__ float g_V[NTOK*HD];

// Split-K partials
__device__ float g_pacc[BB*TILES*NCH_MAX*QT*HD];   // 64 MB
__device__ float g_pm  [BB*TILES*NCH_MAX*QT];
__device__ float g_pl  [BB*TILES*NCH_MAX*QT];

// ---------------------------------------------------------------------------
// Kernel 1: QKV projection as register-blocked SGEMM.
// C[16384, 192] = X[16384,1024] @ W^T, with N split 3x64 (Q/K/V per block).
// BM=128, BN=64, BK=32, 128 threads, 8x8 register tile per thread.
// Smem pad=2 + strided row/col ownership -> conflict-free inner LDS.
// ---------------------------------------------------------------------------
#define GM_BM 128
#define GM_BN 64
#define GM_BK 32
#define GM_LD (GM_BK + 2)   // 34 floats per smem row

__global__ __launch_bounds__(128) void qkv_gemm(
    const float* __restrict__ x,
    const float* __restrict__ Wq,
    const float* __restrict__ Wk,
    const float* __restrict__ Wv)
{
    __shared__ float xs[GM_BM * GM_LD];   // 17.4 KB
    __shared__ float ws[GM_BN * GM_LD];   //  8.7 KB

    const int nblk = blockIdx.x % 3;           // 0=Q, 1=K, 2=V
    const int m0   = (blockIdx.x / 3) * GM_BM; // token base
    const float* W = (nblk == 0) ? Wq : (nblk == 1) ? Wk : Wv;

    const int tid = threadIdx.x;
    const int tr  = tid >> 3;   // 0..15  (thread row)
    const int tc  = tid & 7;    // 0..7   (thread col)

    float acc[8][8];
    #pragma unroll
    for (int i = 0; i < 8; i++)
        #pragma unroll
        for (int j = 0; j < 8; j++) acc[i][j] = 0.f;

    for (int k0 = 0; k0 < DD; k0 += GM_BK) {
        __syncthreads();
        // X tile: 128 rows x 32 k = 1024 float4; 8 per thread, coalesced.
        #pragma unroll
        for (int i = 0; i < 8; i++) {
            int idx = i * 128 + tid;
            int r = idx >> 3;      // row within tile
            int c = idx & 7;       // float4 index within row
            float4 v = *(const float4*)(x + (size_t)(m0 + r) * DD + k0 + c * 4);
            float* p = xs + r * GM_LD + c * 4;
            p[0] = v.x; p[1] = v.y; p[2] = v.z; p[3] = v.w;
        }
        // W tile: 64 rows x 32 k = 512 float4; 4 per thread.
        #pragma unroll
        for (int i = 0; i < 4; i++) {
            int idx = i * 128 + tid;
            int r = idx >> 3;
            int c = idx & 7;
            float4 v = *(const float4*)(W + (size_t)r * DD + k0 + c * 4);
            float* p = ws + r * GM_LD + c * 4;
            p[0] = v.x; p[1] = v.y; p[2] = v.z; p[3] = v.w;
        }
        __syncthreads();

        #pragma unroll 4
        for (int k = 0; k < GM_BK; k++) {
            float xr[8], wr[8];
            #pragma unroll
            for (int i = 0; i < 8; i++) xr[i] = xs[(tr + 16 * i) * GM_LD + k];
            #pragma unroll
            for (int j = 0; j < 8; j++) wr[j] = ws[(tc + 8 * j) * GM_LD + k];
            #pragma unroll
            for (int i = 0; i < 8; i++)
                #pragma unroll
                for (int j = 0; j < 8; j++)
                    acc[i][j] += xr[i] * wr[j];
        }
    }

    float* dst = (nblk == 0) ? g_Q : (nblk == 1) ? g_K : g_V;
    const float qs = (nblk == 0) ? 0.125f : 1.f;   // fold hd^-0.5 into Q
    #pragma unroll
    for (int i = 0; i < 8; i++) {
        const size_t row = m0 + tr + 16 * i;
        #pragma unroll
        for (int j = 0; j < 8; j++)
            dst[row * HD + tc + 8 * j] = acc[i][j] * qs;
    }
}

// ---------------------------------------------------------------------------
// Kernel 2: split-K causal flash attention (partial pass). Unchanged from R2.
// ---------------------------------------------------------------------------
__global__ __launch_bounds__(128) void attn_chunk_kernel()
{
    __shared__ float Ks[KT * HD];
    __shared__ float Vs[KT * HD];

    const int chunk = blockIdx.x;
    const int tile  = blockIdx.y;
    const int b     = blockIdx.z;

    const int kmax = (tile + 1) * QT;
    const int nch  = (kmax + CK - 1) / CK;
    if (chunk >= nch) return;

    const int kstart = chunk * CK;
    const int kend   = min(kstart + CK, kmax);

    const int q0   = tile * QT;
    const int qIdx = q0 + threadIdx.x;

    const float* Qb = g_Q + (size_t)b * TT_SEQ * HD;
    const float* Kb = g_K + (size_t)b * TT_SEQ * HD;
    const float* Vb = g_V + (size_t)b * TT_SEQ * HD;

    float q[HD];
    {
        const float4* qr = (const float4*)(Qb + (size_t)qIdx * HD);
        #pragma unroll
        for (int i = 0; i < 16; i++) {
            float4 v = qr[i];
            q[4*i+0] = v.x; q[4*i+1] = v.y; q[4*i+2] = v.z; q[4*i+3] = v.w;
        }
    }

    float acc[HD];
    #pragma unroll
    for (int i = 0; i < HD; i++) acc[i] = 0.f;
    float mval = -1e30f;
    float lsum = 0.f;

    for (int k0 = kstart; k0 < kend; k0 += KT) {
        __syncthreads();
        {
            const float4* kg = (const float4*)(Kb + (size_t)k0 * HD);
            const float4* vg = (const float4*)(Vb + (size_t)k0 * HD);
            float4* Ks4 = (float4*)Ks;
            float4* Vs4 = (float4*)Vs;
            #pragma unroll 4
            for (int i = threadIdx.x; i < KT * HD / 4; i += QT) {
                Ks4[i] = kg[i];
                Vs4[i] = vg[i];
            }
        }
        __syncthreads();

        for (int j = 0; j < KT; j++) {
            const int kk = k0 + j;
            const float4* kr = (const float4*)(Ks + j * HD);

            float s0 = 0.f, s1 = 0.f, s2 = 0.f, s3 = 0.f;
            #pragma unroll
            for (int i = 0; i < 16; i += 4) {
                float4 a = kr[i+0];
                s0 += a.x*q[4*(i+0)+0] + a.y*q[4*(i+0)+1] + a.z*q[4*(i+0)+2] + a.w*q[4*(i+0)+3];
                float4 bv = kr[i+1];
                s1 += bv.x*q[4*(i+1)+0] + bv.y*q[4*(i+1)+1] + bv.z*q[4*(i+1)+2] + bv.w*q[4*(i+1)+3];
                float4 c = kr[i+2];
                s2 += c.x*q[4*(i+2)+0] + c.y*q[4*(i+2)+1] + c.z*q[4*(i+2)+2] + c.w*q[4*(i+2)+3];
                float4 d = kr[i+3];
                s3 += d.x*q[4*(i+3)+0] + d.y*q[4*(i+3)+1] + d.z*q[4*(i+3)+2] + d.w*q[4*(i+3)+3];
            }
            float s = (s0 + s1) + (s2 + s3);
            s = (kk <= qIdx) ? s : -1e30f;

            const float4* vr = (const float4*)(Vs + j * HD);
            if (s > mval) {
                float scale = __expf(mval - s);
                mval = s;
                lsum = lsum * scale + 1.f;
                #pragma unroll
                for (int i = 0; i < 16; i++) {
                    float4 v = vr[i];
                    acc[4*i+0] = acc[4*i+0] * scale + v.x;
                    acc[4*i+1] = acc[4*i+1] * scale + v.y;
                    acc[4*i+2] = acc[4*i+2] * scale + v.z;
                    acc[4*i+3] = acc[4*i+3] * scale + v.w;
                }
            } else {
                float p = __expf(s - mval);
                lsum += p;
                #pragma unroll
                for (int i = 0; i < 16; i++) {
                    float4 v = vr[i];
                    acc[4*i+0] += p * v.x;
                    acc[4*i+1] += p * v.y;
                    acc[4*i+2] += p * v.z;
                    acc[4*i+3] += p * v.w;
                }
            }
        }
    }

    const size_t pidx = (((size_t)(b * TILES + tile) * NCH_MAX + chunk) * QT) + threadIdx.x;
    g_pm[pidx] = mval;
    g_pl[pidx] = lsum;
    float4* pa = (float4*)(g_pacc + pidx * HD);
    #pragma unroll
    for (int i = 0; i < 16; i++) {
        float4 v;
        v.x = acc[4*i+0]; v.y = acc[4*i+1]; v.z = acc[4*i+2]; v.w = acc[4*i+3];
        pa[i] = v;
    }
}

// ---------------------------------------------------------------------------
// Kernel 3: combine split-K partials. Unchanged from R2.
// ---------------------------------------------------------------------------
__global__ __launch_bounds__(256) void combine_kernel(float* __restrict__ out)
{
    const int gid = blockIdx.x * 256 + threadIdx.x;
    const int q   = gid >> 6;
    const int d   = gid & 63;

    const int b      = q / TT_SEQ;
    const int t_in_b = q % TT_SEQ;
    const int tile   = t_in_b / QT;
    const int qi     = t_in_b % QT;

    const int kmax = (tile + 1) * QT;
    const int nch  = (kmax + CK - 1) / CK;

    const size_t base = ((size_t)(b * TILES + tile) * NCH_MAX) * QT + qi;

    float mstar = -1e30f;
    for (int i = 0; i < nch; i++) {
        float mi = g_pm[base + (size_t)i * QT];
        mstar = fmaxf(mstar, mi);
    }

    float L = 0.f, val = 0.f;
    for (int i = 0; i < nch; i++) {
        const size_t pidx = base + (size_t)i * QT;
        float w = __expf(g_pm[pidx] - mstar);
        L   += g_pl[pidx] * w;
        val += g_pacc[pidx * HD + d] * w;
    }

    out[(size_t)q * HD + d] = val / L;
}

extern "C" void kernel_launch(void* const* d_in, const int* in_sizes, int n_in,
                              void* d_out, int out_size)
{
    const float* x  = (const float*)d_in[0];
    const float* Wq = (const float*)d_in[1];
    const float* Wk = (const float*)d_in[2];
    const float* Wv = (const float*)d_in[3];
    float* out = (float*)d_out;

    qkv_gemm<<<(NTOK / GM_BM) * 3, 128>>>(x, Wq, Wk, Wv);

    dim3 agrid(NCH_MAX, TILES, BB);
    attn_chunk_kernel<<<agrid, QT>>>();

    combine_kernel<<<(NTOK * HD) / 256, 256>>>(out);
}

// round 5
// speedup vs baseline: 3.2940x; 1.1486x over previous
#include <cuda_runtime.h>
#include <cuda_bf16.h>
#include <math.h>
#include <stdint.h>

#define BB 4
#define TT_SEQ 4096
#define DD 1024
#define HD 64
#define NTOK (BB*TT_SEQ)

#define QT 128
#define KT 64
#define CK 256
#define TILES (TT_SEQ/QT)      // 32
#define NCH_MAX (TT_SEQ/CK)    // 16

// Projected Q (pre-scaled by hd^-0.5), K, V. [B*T, HD]
__device__ float g_Q[NTOK*HD];
__device__ float g_K[NTOK*HD];
__device__ float g_V[NTOK*HD];

// W in bf16 hi/lo, rows 0-63=Wq(*0.125), 64-127=Wk, 128-191=Wv
__device__ __nv_bfloat16 g_Whi[3*HD*DD];
__device__ __nv_bfloat16 g_Wlo[3*HD*DD];

// Split-K partials
__device__ float g_pacc[BB*TILES*NCH_MAX*QT*HD];
__device__ float g_pm  [BB*TILES*NCH_MAX*QT];
__device__ float g_pl  [BB*TILES*NCH_MAX*QT];

__device__ __forceinline__ uint32_t pack_bf16(float a, float b) {
    __nv_bfloat162 t = __floats2bfloat162_rn(a, b);
    return *reinterpret_cast<uint32_t*>(&t);
}

// mma.sync m16n8k16 bf16: D(f32) += A(bf16,row) * B(bf16,col)
__device__ __forceinline__ void mma16816(float* d, const uint32_t* a, const uint32_t* b) {
    asm volatile(
        "mma.sync.aligned.m16n8k16.row.col.f32.bf16.bf16.f32 "
        "{%0,%1,%2,%3}, {%4,%5,%6,%7}, {%8,%9}, {%0,%1,%2,%3};"
        : "+f"(d[0]), "+f"(d[1]), "+f"(d[2]), "+f"(d[3])
        : "r"(a[0]), "r"(a[1]), "r"(a[2]), "r"(a[3]),
          "r"(b[0]), "r"(b[1]));
}

// ---------------------------------------------------------------------------
// Kernel 0: convert W (fp32 -> bf16 hi/lo), fold 1/8 into Wq.
// ---------------------------------------------------------------------------
__global__ __launch_bounds__(256) void convert_w(
    const float* __restrict__ Wq,
    const float* __restrict__ Wk,
    const float* __restrict__ Wv)
{
    const int idx = blockIdx.x * 256 + threadIdx.x;
    const int e0  = idx * 4;
    const int row = e0 >> 10;
    const int col = e0 & 1023;
    const float* src = (row < 64) ? Wq + (size_t)row * DD
                     : (row < 128) ? Wk + (size_t)(row - 64) * DD
                                   : Wv + (size_t)(row - 128) * DD;
    const float sc = (row < 64) ? 0.125f : 1.0f;
    float4 v = *(const float4*)(src + col);
    v.x *= sc; v.y *= sc; v.z *= sc; v.w *= sc;

    float h0 = __bfloat162float(__float2bfloat16_rn(v.x));
    float h1 = __bfloat162float(__float2bfloat16_rn(v.y));
    float h2 = __bfloat162float(__float2bfloat16_rn(v.z));
    float h3 = __bfloat162float(__float2bfloat16_rn(v.w));

    uint2 hi, lo;
    hi.x = pack_bf16(v.x, v.y);           hi.y = pack_bf16(v.z, v.w);
    lo.x = pack_bf16(v.x - h0, v.y - h1); lo.y = pack_bf16(v.z - h2, v.w - h3);

    *(uint2*)(g_Whi + e0) = hi;
    *(uint2*)(g_Wlo + e0) = lo;
}

// ---------------------------------------------------------------------------
// Kernel 1: QKV projection via mma.sync (bf16 hi/lo split).
// BM=128, BN=64 (one of Q/K/V per block), BK=32. 8 warps, 4x2 layout,
// each warp owns a 32x32 output tile. Direct LDS fragment loads,
// stride 40 bf16 (20 words) -> conflict-free.
// ---------------------------------------------------------------------------
#define GM_BM 128
#define GM_BN 64
#define GM_BK 32
#define XLD 40
#define WLD 40

__global__ __launch_bounds__(256) void qkv_hmma(const float* __restrict__ x)
{
    __shared__ __nv_bfloat16 xhi[GM_BM * XLD];   // 10 KB
    __shared__ __nv_bfloat16 xlo[GM_BM * XLD];   // 10 KB
    __shared__ __nv_bfloat16 whi[GM_BN * WLD];   // 5 KB
    __shared__ __nv_bfloat16 wlo[GM_BN * WLD];   // 5 KB

    const int nblk = blockIdx.x % 3;             // 0=Q, 1=K, 2=V
    const int m0   = (blockIdx.x / 3) * GM_BM;

    const int tid  = threadIdx.x;
    const int warp = tid >> 5;
    const int lane = tid & 31;
    const int wm   = (warp & 3) * 32;            // warp M offset
    const int wn   = (warp >> 2) * 32;           // warp N offset
    const int g    = lane >> 2;                  // fragment group row
    const int t4   = lane & 3;

    float acc[2][4][4];
    #pragma unroll
    for (int mi = 0; mi < 2; mi++)
        #pragma unroll
        for (int ni = 0; ni < 4; ni++)
            #pragma unroll
            for (int k = 0; k < 4; k++) acc[mi][ni][k] = 0.f;

    const int xr = tid >> 1;     // X row this thread loads
    const int xp = tid & 1;      // 16-float half

    for (int k0 = 0; k0 < DD; k0 += GM_BK) {
        __syncthreads();
        // X: 128 x 32 fp32 -> bf16 hi/lo
        {
            const float4* src = (const float4*)(x + (size_t)(m0 + xr) * DD + k0 + xp * 16);
            #pragma unroll
            for (int i = 0; i < 4; i++) {
                float4 v = src[i];
                float h0 = __bfloat162float(__float2bfloat16_rn(v.x));
                float h1 = __bfloat162float(__float2bfloat16_rn(v.y));
                float h2 = __bfloat162float(__float2bfloat16_rn(v.z));
                float h3 = __bfloat162float(__float2bfloat16_rn(v.w));
                const int o = xr * XLD + xp * 16 + i * 4;
                *(uint32_t*)(xhi + o + 0) = pack_bf16(v.x, v.y);
                *(uint32_t*)(xhi + o + 2) = pack_bf16(v.z, v.w);
                *(uint32_t*)(xlo + o + 0) = pack_bf16(v.x - h0, v.y - h1);
                *(uint32_t*)(xlo + o + 2) = pack_bf16(v.z - h2, v.w - h3);
            }
        }
        // W hi/lo: 64 x 32 bf16 each; 8 contiguous bf16 per thread (uint4)
        {
            const int wr = tid >> 2;
            const int wc = (tid & 3) * 8;
            const size_t gof = (size_t)(nblk * 64 + wr) * DD + k0 + wc;
            *(uint4*)(whi + wr * WLD + wc) = *(const uint4*)(g_Whi + gof);
            *(uint4*)(wlo + wr * WLD + wc) = *(const uint4*)(g_Wlo + gof);
        }
        __syncthreads();

        #pragma unroll
        for (int kk = 0; kk < GM_BK; kk += 16) {
            uint32_t ahi[2][4], alo[2][4], bhi[4][2], blo[4][2];
            // A fragments (hi): a0=(g,k) a1=(g+8,k) a2=(g,k+8) a3=(g+8,k+8)
            #pragma unroll
            for (int mi = 0; mi < 2; mi++) {
                const int rb = wm + mi * 16 + g;
                const int cb = kk + 2 * t4;
                ahi[mi][0] = *(const uint32_t*)(xhi + rb * XLD + cb);
                ahi[mi][1] = *(const uint32_t*)(xhi + (rb + 8) * XLD + cb);
                ahi[mi][2] = *(const uint32_t*)(xhi + rb * XLD + cb + 8);
                ahi[mi][3] = *(const uint32_t*)(xhi + (rb + 8) * XLD + cb + 8);
            }
            // B fragments (hi): b0=(k,n) pairs from W[n][k] row-major
            #pragma unroll
            for (int ni = 0; ni < 4; ni++) {
                const int nr = wn + ni * 8 + g;
                const int cb = kk + 2 * t4;
                bhi[ni][0] = *(const uint32_t*)(whi + nr * WLD + cb);
                bhi[ni][1] = *(const uint32_t*)(whi + nr * WLD + cb + 8);
            }
            // term 0: Ahi * Bhi
            #pragma unroll
            for (int mi = 0; mi < 2; mi++)
                #pragma unroll
                for (int ni = 0; ni < 4; ni++)
                    mma16816(acc[mi][ni], ahi[mi], bhi[ni]);
            // term 1: Ahi * Blo
            #pragma unroll
            for (int ni = 0; ni < 4; ni++) {
                const int nr = wn + ni * 8 + g;
                const int cb = kk + 2 * t4;
                blo[ni][0] = *(const uint32_t*)(wlo + nr * WLD + cb);
                blo[ni][1] = *(const uint32_t*)(wlo + nr * WLD + cb + 8);
            }
            #pragma unroll
            for (int mi = 0; mi < 2; mi++)
                #pragma unroll
                for (int ni = 0; ni < 4; ni++)
                    mma16816(acc[mi][ni], ahi[mi], blo[ni]);
            // term 2: Alo * Bhi
            #pragma unroll
            for (int mi = 0; mi < 2; mi++) {
                const int rb = wm + mi * 16 + g;
                const int cb = kk + 2 * t4;
                alo[mi][0] = *(const uint32_t*)(xlo + rb * XLD + cb);
                alo[mi][1] = *(const uint32_t*)(xlo + (rb + 8) * XLD + cb);
                alo[mi][2] = *(const uint32_t*)(xlo + rb * XLD + cb + 8);
                alo[mi][3] = *(const uint32_t*)(xlo + (rb + 8) * XLD + cb + 8);
            }
            #pragma unroll
            for (int mi = 0; mi < 2; mi++)
                #pragma unroll
                for (int ni = 0; ni < 4; ni++)
                    mma16816(acc[mi][ni], alo[mi], bhi[ni]);
        }
    }

    // epilogue: c frag (m16n8): c0=(g, 2t) c1=(g, 2t+1) c2=(g+8, 2t) c3=(g+8, 2t+1)
    float* dst = (nblk == 0) ? g_Q : (nblk == 1) ? g_K : g_V;
    #pragma unroll
    for (int mi = 0; mi < 2; mi++) {
        #pragma unroll
        for (int ni = 0; ni < 4; ni++) {
            const size_t r0 = (size_t)m0 + wm + mi * 16 + g;
            const int    c  = wn + ni * 8 + 2 * t4;
            float2 lo2, hi2;
            lo2.x = acc[mi][ni][0]; lo2.y = acc[mi][ni][1];
            hi2.x = acc[mi][ni][2]; hi2.y = acc[mi][ni][3];
            *(float2*)(dst + r0 * HD + c)       = lo2;
            *(float2*)(dst + (r0 + 8) * HD + c) = hi2;
        }
    }
}

// ---------------------------------------------------------------------------
// Kernel 2: split-K causal flash attention (unchanged from R3).
// ---------------------------------------------------------------------------
__global__ __launch_bounds__(128) void attn_chunk_kernel()
{
    __shared__ float Ks[KT * HD];
    __shared__ float Vs[KT * HD];

    const int chunk = blockIdx.x;
    const int tile  = blockIdx.y;
    const int b     = blockIdx.z;

    const int kmax = (tile + 1) * QT;
    const int nch  = (kmax + CK - 1) / CK;
    if (chunk >= nch) return;

    const int kstart = chunk * CK;
    const int kend   = min(kstart + CK, kmax);

    const int q0   = tile * QT;
    const int qIdx = q0 + threadIdx.x;

    const float* Qb = g_Q + (size_t)b * TT_SEQ * HD;
    const float* Kb = g_K + (size_t)b * TT_SEQ * HD;
    const float* Vb = g_V + (size_t)b * TT_SEQ * HD;

    float q[HD];
    {
        const float4* qr = (const float4*)(Qb + (size_t)qIdx * HD);
        #pragma unroll
        for (int i = 0; i < 16; i++) {
            float4 v = qr[i];
            q[4*i+0] = v.x; q[4*i+1] = v.y; q[4*i+2] = v.z; q[4*i+3] = v.w;
        }
    }

    float acc[HD];
    #pragma unroll
    for (int i = 0; i < HD; i++) acc[i] = 0.f;
    float mval = -1e30f;
    float lsum = 0.f;

    for (int k0 = kstart; k0 < kend; k0 += KT) {
        __syncthreads();
        {
            const float4* kg = (const float4*)(Kb + (size_t)k0 * HD);
            const float4* vg = (const float4*)(Vb + (size_t)k0 * HD);
            float4* Ks4 = (float4*)Ks;
            float4* Vs4 = (float4*)Vs;
            #pragma unroll 4
            for (int i = threadIdx.x; i < KT * HD / 4; i += QT) {
                Ks4[i] = kg[i];
                Vs4[i] = vg[i];
            }
        }
        __syncthreads();

        for (int j = 0; j < KT; j++) {
            const int kk = k0 + j;
            const float4* kr = (const float4*)(Ks + j * HD);

            float s0 = 0.f, s1 = 0.f, s2 = 0.f, s3 = 0.f;
            #pragma unroll
            for (int i = 0; i < 16; i += 4) {
                float4 a = kr[i+0];
                s0 += a.x*q[4*(i+0)+0] + a.y*q[4*(i+0)+1] + a.z*q[4*(i+0)+2] + a.w*q[4*(i+0)+3];
                float4 bv = kr[i+1];
                s1 += bv.x*q[4*(i+1)+0] + bv.y*q[4*(i+1)+1] + bv.z*q[4*(i+1)+2] + bv.w*q[4*(i+1)+3];
                float4 c = kr[i+2];
                s2 += c.x*q[4*(i+2)+0] + c.y*q[4*(i+2)+1] + c.z*q[4*(i+2)+2] + c.w*q[4*(i+2)+3];
                float4 d = kr[i+3];
                s3 += d.x*q[4*(i+3)+0] + d.y*q[4*(i+3)+1] + d.z*q[4*(i+3)+2] + d.w*q[4*(i+3)+3];
            }
            float s = (s0 + s1) + (s2 + s3);
            s = (kk <= qIdx) ? s : -1e30f;

            const float4* vr = (const float4*)(Vs + j * HD);
            if (s > mval) {
                float scale = __expf(mval - s);
                mval = s;
                lsum = lsum * scale + 1.f;
                #pragma unroll
                for (int i = 0; i < 16; i++) {
                    float4 v = vr[i];
                    acc[4*i+0] = acc[4*i+0] * scale + v.x;
                    acc[4*i+1] = acc[4*i+1] * scale + v.y;
                    acc[4*i+2] = acc[4*i+2] * scale + v.z;
                    acc[4*i+3] = acc[4*i+3] * scale + v.w;
                }
            } else {
                float p = __expf(s - mval);
                lsum += p;
                #pragma unroll
                for (int i = 0; i < 16; i++) {
                    float4 v = vr[i];
                    acc[4*i+0] += p * v.x;
                    acc[4*i+1] += p * v.y;
                    acc[4*i+2] += p * v.z;
                    acc[4*i+3] += p * v.w;
                }
            }
        }
    }

    const size_t pidx = (((size_t)(b * TILES + tile) * NCH_MAX + chunk) * QT) + threadIdx.x;
    g_pm[pidx] = mval;
    g_pl[pidx] = lsum;
    float4* pa = (float4*)(g_pacc + pidx * HD);
    #pragma unroll
    for (int i = 0; i < 16; i++) {
        float4 v;
        v.x = acc[4*i+0]; v.y = acc[4*i+1]; v.z = acc[4*i+2]; v.w = acc[4*i+3];
        pa[i] = v;
    }
}

// ---------------------------------------------------------------------------
// Kernel 3: combine split-K partials (unchanged).
// ---------------------------------------------------------------------------
__global__ __launch_bounds__(256) void combine_kernel(float* __restrict__ out)
{
    const int gid = blockIdx.x * 256 + threadIdx.x;
    const int q   = gid >> 6;
    const int d   = gid & 63;

    const int b      = q / TT_SEQ;
    const int t_in_b = q % TT_SEQ;
    const int tile   = t_in_b / QT;
    const int qi     = t_in_b % QT;

    const int kmax = (tile + 1) * QT;
    const int nch  = (kmax + CK - 1) / CK;

    const size_t base = ((size_t)(b * TILES + tile) * NCH_MAX) * QT + qi;

    float mstar = -1e30f;
    for (int i = 0; i < nch; i++) {
        float mi = g_pm[base + (size_t)i * QT];
        mstar = fmaxf(mstar, mi);
    }

    float L = 0.f, val = 0.f;
    for (int i = 0; i < nch; i++) {
        const size_t pidx = base + (size_t)i * QT;
        float w = __expf(g_pm[pidx] - mstar);
        L   += g_pl[pidx] * w;
        val += g_pacc[pidx * HD + d] * w;
    }

    out[(size_t)q * HD + d] = val / L;
}

extern "C" void kernel_launch(void* const* d_in, const int* in_sizes, int n_in,
                              void* d_out, int out_size)
{
    const float* x  = (const float*)d_in[0];
    const float* Wq = (const float*)d_in[1];
    const float* Wk = (const float*)d_in[2];
    const float* Wv = (const float*)d_in[3];
    float* out = (float*)d_out;

    convert_w<<<(3 * HD * DD / 4) / 256, 256>>>(Wq, Wk, Wv);
    qkv_hmma<<<(NTOK / GM_BM) * 3, 256>>>(x);

    dim3 agrid(NCH_MAX, TILES, BB);
    attn_chunk_kernel<<<agrid, QT>>>();

    combine_kernel<<<(NTOK * HD) / 256, 256>>>(out);
}

// round 6
// speedup vs baseline: 6.3924x; 1.9406x over previous
#include <cuda_runtime.h>
#include <cuda_bf16.h>
#include <math.h>
#include <stdint.h>

#define BB 4
#define TT_SEQ 4096
#define DD 1024
#define HD 64
#define NTOK (BB*TT_SEQ)

#define QT 128
#define CK 256
#define TILES (TT_SEQ/QT)      // 32
#define NCH_MAX (TT_SEQ/CK)    // 16

// Projected Q (pre-scaled by hd^-0.5), K, V. [B*T, HD]
__device__ float g_Q[NTOK*HD];
__device__ float g_K[NTOK*HD];
__device__ float g_V[NTOK*HD];

// W in bf16 hi/lo, rows 0-63=Wq(*0.125), 64-127=Wk, 128-191=Wv
__device__ __nv_bfloat16 g_Whi[3*HD*DD];
__device__ __nv_bfloat16 g_Wlo[3*HD*DD];

// Split-K partials
__device__ float g_pacc[BB*TILES*NCH_MAX*QT*HD];
__device__ float g_pm  [BB*TILES*NCH_MAX*QT];
__device__ float g_pl  [BB*TILES*NCH_MAX*QT];

__device__ __forceinline__ uint32_t pack_bf16(float a, float b) {
    __nv_bfloat162 t = __floats2bfloat162_rn(a, b);
    return *reinterpret_cast<uint32_t*>(&t);
}

// split pair of fp32 into packed bf16 hi and residual lo
__device__ __forceinline__ void split2(float a, float b, uint32_t& hi, uint32_t& lo) {
    __nv_bfloat162 h = __floats2bfloat162_rn(a, b);
    hi = *reinterpret_cast<uint32_t*>(&h);
    lo = pack_bf16(a - __bfloat162float(h.x), b - __bfloat162float(h.y));
}

// mma.sync m16n8k16 bf16: D(f32) += A(bf16,row) * B(bf16,col)
__device__ __forceinline__ void mma16816(float* d, const uint32_t* a, const uint32_t* b) {
    asm volatile(
        "mma.sync.aligned.m16n8k16.row.col.f32.bf16.bf16.f32 "
        "{%0,%1,%2,%3}, {%4,%5,%6,%7}, {%8,%9}, {%0,%1,%2,%3};"
        : "+f"(d[0]), "+f"(d[1]), "+f"(d[2]), "+f"(d[3])
        : "r"(a[0]), "r"(a[1]), "r"(a[2]), "r"(a[3]),
          "r"(b[0]), "r"(b[1]));
}

// ---------------------------------------------------------------------------
// Kernel 0: convert W (fp32 -> bf16 hi/lo), fold 1/8 into Wq.
// ---------------------------------------------------------------------------
__global__ __launch_bounds__(256) void convert_w(
    const float* __restrict__ Wq,
    const float* __restrict__ Wk,
    const float* __restrict__ Wv)
{
    const int idx = blockIdx.x * 256 + threadIdx.x;
    const int e0  = idx * 4;
    const int row = e0 >> 10;
    const int col = e0 & 1023;
    const float* src = (row < 64) ? Wq + (size_t)row * DD
                     : (row < 128) ? Wk + (size_t)(row - 64) * DD
                                   : Wv + (size_t)(row - 128) * DD;
    const float sc = (row < 64) ? 0.125f : 1.0f;
    float4 v = *(const float4*)(src + col);
    v.x *= sc; v.y *= sc; v.z *= sc; v.w *= sc;

    uint2 hi, lo;
    split2(v.x, v.y, hi.x, lo.x);
    split2(v.z, v.w, hi.y, lo.y);

    *(uint2*)(g_Whi + e0) = hi;
    *(uint2*)(g_Wlo + e0) = lo;
}

// ---------------------------------------------------------------------------
// Kernel 1: QKV projection via mma.sync (bf16 hi/lo split). Unchanged from R5.
// ---------------------------------------------------------------------------
#define GM_BM 128
#define GM_BN 64
#define GM_BK 32
#define XLD 40
#define WLD 40

__global__ __launch_bounds__(256) void qkv_hmma(const float* __restrict__ x)
{
    __shared__ __nv_bfloat16 xhi[GM_BM * XLD];
    __shared__ __nv_bfloat16 xlo[GM_BM * XLD];
    __shared__ __nv_bfloat16 whi[GM_BN * WLD];
    __shared__ __nv_bfloat16 wlo[GM_BN * WLD];

    const int nblk = blockIdx.x % 3;
    const int m0   = (blockIdx.x / 3) * GM_BM;

    const int tid  = threadIdx.x;
    const int warp = tid >> 5;
    const int lane = tid & 31;
    const int wm   = (warp & 3) * 32;
    const int wn   = (warp >> 2) * 32;
    const int g    = lane >> 2;
    const int t4   = lane & 3;

    float acc[2][4][4];
    #pragma unroll
    for (int mi = 0; mi < 2; mi++)
        #pragma unroll
        for (int ni = 0; ni < 4; ni++)
            #pragma unroll
            for (int k = 0; k < 4; k++) acc[mi][ni][k] = 0.f;

    const int xr = tid >> 1;
    const int xp = tid & 1;

    for (int k0 = 0; k0 < DD; k0 += GM_BK) {
        __syncthreads();
        {
            const float4* src = (const float4*)(x + (size_t)(m0 + xr) * DD + k0 + xp * 16);
            #pragma unroll
            for (int i = 0; i < 4; i++) {
                float4 v = src[i];
                const int o = xr * XLD + xp * 16 + i * 4;
                uint32_t h0, l0, h1, l1;
                split2(v.x, v.y, h0, l0);
                split2(v.z, v.w, h1, l1);
                *(uint32_t*)(xhi + o + 0) = h0;
                *(uint32_t*)(xhi + o + 2) = h1;
                *(uint32_t*)(xlo + o + 0) = l0;
                *(uint32_t*)(xlo + o + 2) = l1;
            }
        }
        {
            const int wr = tid >> 2;
            const int wc = (tid & 3) * 8;
            const size_t gof = (size_t)(nblk * 64 + wr) * DD + k0 + wc;
            *(uint4*)(whi + wr * WLD + wc) = *(const uint4*)(g_Whi + gof);
            *(uint4*)(wlo + wr * WLD + wc) = *(const uint4*)(g_Wlo + gof);
        }
        __syncthreads();

        #pragma unroll
        for (int kk = 0; kk < GM_BK; kk += 16) {
            uint32_t ahi[2][4], alo[2][4], bhi[4][2], blo[4][2];
            #pragma unroll
            for (int mi = 0; mi < 2; mi++) {
                const int rb = wm + mi * 16 + g;
                const int cb = kk + 2 * t4;
                ahi[mi][0] = *(const uint32_t*)(xhi + rb * XLD + cb);
                ahi[mi][1] = *(const uint32_t*)(xhi + (rb + 8) * XLD + cb);
                ahi[mi][2] = *(const uint32_t*)(xhi + rb * XLD + cb + 8);
                ahi[mi][3] = *(const uint32_t*)(xhi + (rb + 8) * XLD + cb + 8);
            }
            #pragma unroll
            for (int ni = 0; ni < 4; ni++) {
                const int nr = wn + ni * 8 + g;
                const int cb = kk + 2 * t4;
                bhi[ni][0] = *(const uint32_t*)(whi + nr * WLD + cb);
                bhi[ni][1] = *(const uint32_t*)(whi + nr * WLD + cb + 8);
            }
            #pragma unroll
            for (int mi = 0; mi < 2; mi++)
                #pragma unroll
                for (int ni = 0; ni < 4; ni++)
                    mma16816(acc[mi][ni], ahi[mi], bhi[ni]);
            #pragma unroll
            for (int ni = 0; ni < 4; ni++) {
                const int nr = wn + ni * 8 + g;
                const int cb = kk + 2 * t4;
                blo[ni][0] = *(const uint32_t*)(wlo + nr * WLD + cb);
                blo[ni][1] = *(const uint32_t*)(wlo + nr * WLD + cb + 8);
            }
            #pragma unroll
            for (int mi = 0; mi < 2; mi++)
                #pragma unroll
                for (int ni = 0; ni < 4; ni++)
                    mma16816(acc[mi][ni], ahi[mi], blo[ni]);
            #pragma unroll
            for (int mi = 0; mi < 2; mi++) {
                const int rb = wm + mi * 16 + g;
                const int cb = kk + 2 * t4;
                alo[mi][0] = *(const uint32_t*)(xlo + rb * XLD + cb);
                alo[mi][1] = *(const uint32_t*)(xlo + (rb + 8) * XLD + cb);
                alo[mi][2] = *(const uint32_t*)(xlo + rb * XLD + cb + 8);
                alo[mi][3] = *(const uint32_t*)(xlo + (rb + 8) * XLD + cb + 8);
            }
            #pragma unroll
            for (int mi = 0; mi < 2; mi++)
                #pragma unroll
                for (int ni = 0; ni < 4; ni++)
                    mma16816(acc[mi][ni], alo[mi], bhi[ni]);
        }
    }

    float* dst = (nblk == 0) ? g_Q : (nblk == 1) ? g_K : g_V;
    #pragma unroll
    for (int mi = 0; mi < 2; mi++) {
        #pragma unroll
        for (int ni = 0; ni < 4; ni++) {
            const size_t r0 = (size_t)m0 + wm + mi * 16 + g;
            const int    c  = wn + ni * 8 + 2 * t4;
            float2 lo2, hi2;
            lo2.x = acc[mi][ni][0]; lo2.y = acc[mi][ni][1];
            hi2.x = acc[mi][ni][2]; hi2.y = acc[mi][ni][3];
            *(float2*)(dst + r0 * HD + c)       = lo2;
            *(float2*)(dst + (r0 + 8) * HD + c) = hi2;
        }
    }
}

// ---------------------------------------------------------------------------
// Kernel 2: split-K causal flash attention on mma.sync.
// CTA = (chunk, tile, b); 4 warps x 32 query rows. Q frags in registers
// (hi/lo). K smem row-major, V smem transposed [hd][key]; TLD=72 makes all
// fragment LDS bank-conflict-free. 3-term hi/lo mma for S and PV.
// ---------------------------------------------------------------------------
#define TLD 72

__global__ __launch_bounds__(128) void attn_mma()
{
    __shared__ __nv_bfloat16 khi[64 * TLD];
    __shared__ __nv_bfloat16 klo[64 * TLD];
    __shared__ __nv_bfloat16 vhi[64 * TLD];   // transposed: [hd][key]
    __shared__ __nv_bfloat16 vlo[64 * TLD];

    const int chunk = blockIdx.x;
    const int tile  = blockIdx.y;
    const int b     = blockIdx.z;

    const int kmax = (tile + 1) * QT;
    const int nch  = (kmax + CK - 1) / CK;
    if (chunk >= nch) return;

    const int kstart = chunk * CK;
    const int kend   = min(kstart + CK, kmax);
    const int q0     = tile * QT;

    const int tid  = threadIdx.x;
    const int warp = tid >> 5;
    const int lane = tid & 31;
    const int g    = lane >> 2;
    const int t4   = lane & 3;

    const float* Qb = g_Q + (size_t)b * TT_SEQ * HD;
    const float* Kb = g_K + (size_t)b * TT_SEQ * HD;
    const float* Vb = g_V + (size_t)b * TT_SEQ * HD;

    // ---- Q fragments: load once from global, split hi/lo ----
    uint32_t Qh[2][4][4], Ql[2][4][4];
    #pragma unroll
    for (int mi = 0; mi < 2; mi++) {
        const int ar = q0 + warp * 32 + mi * 16 + g;
        const float* r0 = Qb + (size_t)ar * HD;
        const float* r1 = r0 + 8 * HD;
        #pragma unroll
        for (int ks = 0; ks < 4; ks++) {
            const int c = ks * 16 + 2 * t4;
            float2 v00 = *(const float2*)(r0 + c);
            float2 v10 = *(const float2*)(r1 + c);
            float2 v01 = *(const float2*)(r0 + c + 8);
            float2 v11 = *(const float2*)(r1 + c + 8);
            split2(v00.x, v00.y, Qh[mi][ks][0], Ql[mi][ks][0]);
            split2(v10.x, v10.y, Qh[mi][ks][1], Ql[mi][ks][1]);
            split2(v01.x, v01.y, Qh[mi][ks][2], Ql[mi][ks][2]);
            split2(v11.x, v11.y, Qh[mi][ks][3], Ql[mi][ks][3]);
        }
    }

    float o[2][8][4];
    #pragma unroll
    for (int mi = 0; mi < 2; mi++)
        #pragma unroll
        for (int ni = 0; ni < 8; ni++)
            #pragma unroll
            for (int e = 0; e < 4; e++) o[mi][ni][e] = 0.f;
    float m_[2][2] = {{-1e20f, -1e20f}, {-1e20f, -1e20f}};
    float l_[2][2] = {{0.f, 0.f}, {0.f, 0.f}};

    for (int k0 = kstart; k0 < kend; k0 += 64) {
        __syncthreads();
        // ---- stage K (row-major) and V (transposed) as bf16 hi/lo ----
        {
            const int row  = tid >> 1;            // key index 0..63
            const int half = (tid & 1) * 32;      // hd half
            const float4* ksrc = (const float4*)(Kb + (size_t)(k0 + row) * HD + half);
            #pragma unroll
            for (int i = 0; i < 8; i++) {
                float4 v = ksrc[i];
                uint32_t h0, l0, h1, l1;
                split2(v.x, v.y, h0, l0);
                split2(v.z, v.w, h1, l1);
                const int off = row * TLD + half + i * 4;
                *(uint32_t*)(khi + off + 0) = h0;
                *(uint32_t*)(khi + off + 2) = h1;
                *(uint32_t*)(klo + off + 0) = l0;
                *(uint32_t*)(klo + off + 2) = l1;
            }
            const float4* vsrc = (const float4*)(Vb + (size_t)(k0 + row) * HD + half);
            #pragma unroll
            for (int i = 0; i < 8; i++) {
                float4 v = vsrc[i];
                float f[4] = {v.x, v.y, v.z, v.w};
                #pragma unroll
                for (int j = 0; j < 4; j++) {
                    const int hd = half + i * 4 + j;
                    __nv_bfloat16 h = __float2bfloat16_rn(f[j]);
                    vhi[hd * TLD + row] = h;
                    vlo[hd * TLD + row] = __float2bfloat16_rn(f[j] - __bfloat162float(h));
                }
            }
        }
        __syncthreads();

        #pragma unroll
        for (int mi = 0; mi < 2; mi++) {
            const int rbase = warp * 32 + mi * 16;

            // ---- S = Q K^T (3 hi/lo terms) ----
            float s[8][4];
            #pragma unroll
            for (int ni = 0; ni < 8; ni++)
                #pragma unroll
                for (int e = 0; e < 4; e++) s[ni][e] = 0.f;

            #pragma unroll
            for (int ks = 0; ks < 4; ks++) {
                const int cb = ks * 16 + 2 * t4;
                #pragma unroll
                for (int ni = 0; ni < 8; ni++) {
                    const int nr = ni * 8 + g;
                    uint32_t bh[2], bl[2];
                    bh[0] = *(const uint32_t*)(khi + nr * TLD + cb);
                    bh[1] = *(const uint32_t*)(khi + nr * TLD + cb + 8);
                    bl[0] = *(const uint32_t*)(klo + nr * TLD + cb);
                    bl[1] = *(const uint32_t*)(klo + nr * TLD + cb + 8);
                    mma16816(s[ni], Qh[mi][ks], bh);
                    mma16816(s[ni], Qh[mi][ks], bl);
                    mma16816(s[ni], Ql[mi][ks], bh);
                }
            }

            // ---- causal mask (only needed near the diagonal) ----
            if (k0 + 63 > q0 + rbase) {
                const int qa = q0 + rbase + g;
                #pragma unroll
                for (int ni = 0; ni < 8; ni++) {
                    const int kc = k0 + ni * 8 + 2 * t4;
                    if (kc     > qa)     s[ni][0] = -1e30f;
                    if (kc + 1 > qa)     s[ni][1] = -1e30f;
                    if (kc     > qa + 8) s[ni][2] = -1e30f;
                    if (kc + 1 > qa + 8) s[ni][3] = -1e30f;
                }
            }

            // ---- online softmax on C-fragment layout ----
            float mxA = -1e30f, mxB = -1e30f;
            #pragma unroll
            for (int ni = 0; ni < 8; ni++) {
                mxA = fmaxf(mxA, fmaxf(s[ni][0], s[ni][1]));
                mxB = fmaxf(mxB, fmaxf(s[ni][2], s[ni][3]));
            }
            mxA = fmaxf(mxA, __shfl_xor_sync(0xffffffffu, mxA, 1));
            mxA = fmaxf(mxA, __shfl_xor_sync(0xffffffffu, mxA, 2));
            mxB = fmaxf(mxB, __shfl_xor_sync(0xffffffffu, mxB, 1));
            mxB = fmaxf(mxB, __shfl_xor_sync(0xffffffffu, mxB, 2));

            const float mA = fmaxf(m_[mi][0], mxA);
            const float mB = fmaxf(m_[mi][1], mxB);
            const float scA = __expf(m_[mi][0] - mA);
            const float scB = __expf(m_[mi][1] - mB);
            m_[mi][0] = mA; m_[mi][1] = mB;

            uint32_t Ph[4][4], Pl[4][4];
            float sA = 0.f, sB = 0.f;
            #pragma unroll
            for (int ni = 0; ni < 8; ni++) {
                float p0 = __expf(s[ni][0] - mA);
                float p1 = __expf(s[ni][1] - mA);
                float p2 = __expf(s[ni][2] - mB);
                float p3 = __expf(s[ni][3] - mB);
                sA += p0 + p1; sB += p2 + p3;
                const int ks   = ni >> 1;
                const int base = (ni & 1) * 2;
                split2(p0, p1, Ph[ks][base + 0], Pl[ks][base + 0]);
                split2(p2, p3, Ph[ks][base + 1], Pl[ks][base + 1]);
            }
            sA += __shfl_xor_sync(0xffffffffu, sA, 1);
            sA += __shfl_xor_sync(0xffffffffu, sA, 2);
            sB += __shfl_xor_sync(0xffffffffu, sB, 1);
            sB += __shfl_xor_sync(0xffffffffu, sB, 2);
            l_[mi][0] = l_[mi][0] * scA + sA;
            l_[mi][1] = l_[mi][1] * scB + sB;

            #pragma unroll
            for (int ni = 0; ni < 8; ni++) {
                o[mi][ni][0] *= scA; o[mi][ni][1] *= scA;
                o[mi][ni][2] *= scB; o[mi][ni][3] *= scB;
            }

            // ---- O += P V (3 hi/lo terms) ----
            #pragma unroll
            for (int ks = 0; ks < 4; ks++) {
                const int vc = ks * 16 + 2 * t4;
                #pragma unroll
                for (int ni = 0; ni < 8; ni++) {
                    const int nr = ni * 8 + g;
                    uint32_t bh[2], bl[2];
                    bh[0] = *(const uint32_t*)(vhi + nr * TLD + vc);
                    bh[1] = *(const uint32_t*)(vhi + nr * TLD + vc + 8);
                    bl[0] = *(const uint32_t*)(vlo + nr * TLD + vc);
                    bl[1] = *(const uint32_t*)(vlo + nr * TLD + vc + 8);
                    mma16816(o[mi][ni], Ph[ks], bh);
                    mma16816(o[mi][ni], Ph[ks], bl);
                    mma16816(o[mi][ni], Pl[ks], bh);
                }
            }
        }
    }

    // ---- write partials ----
    const size_t pbase = ((size_t)(b * TILES + tile) * NCH_MAX + chunk) * QT;
    #pragma unroll
    for (int mi = 0; mi < 2; mi++) {
        const int lrA = warp * 32 + mi * 16 + g;
        if (t4 == 0) {
            g_pm[pbase + lrA]     = m_[mi][0];
            g_pl[pbase + lrA]     = l_[mi][0];
            g_pm[pbase + lrA + 8] = m_[mi][1];
            g_pl[pbase + lrA + 8] = l_[mi][1];
        }
        #pragma unroll
        for (int ni = 0; ni < 8; ni++) {
            const int c = ni * 8 + 2 * t4;
            float2 vA, vB;
            vA.x = o[mi][ni][0]; vA.y = o[mi][ni][1];
            vB.x = o[mi][ni][2]; vB.y = o[mi][ni][3];
            *(float2*)(g_pacc + (pbase + lrA) * HD + c)       = vA;
            *(float2*)(g_pacc + (pbase + lrA + 8) * HD + c)   = vB;
        }
    }
}

// ---------------------------------------------------------------------------
// Kernel 3: combine split-K partials (unchanged).
// ---------------------------------------------------------------------------
__global__ __launch_bounds__(256) void combine_kernel(float* __restrict__ out)
{
    const int gid = blockIdx.x * 256 + threadIdx.x;
    const int q   = gid >> 6;
    const int d   = gid & 63;

    const int b      = q / TT_SEQ;
    const int t_in_b = q % TT_SEQ;
    const int tile   = t_in_b / QT;
    const int qi     = t_in_b % QT;

    const int kmax = (tile + 1) * QT;
    const int nch  = (kmax + CK - 1) / CK;

    const size_t base = ((size_t)(b * TILES + tile) * NCH_MAX) * QT + qi;

    float mstar = -1e30f;
    for (int i = 0; i < nch; i++) {
        float mi = g_pm[base + (size_t)i * QT];
        mstar = fmaxf(mstar, mi);
    }

    float L = 0.f, val = 0.f;
    for (int i = 0; i < nch; i++) {
        const size_t pidx = base + (size_t)i * QT;
        float w = __expf(g_pm[pidx] - mstar);
        L   += g_pl[pidx] * w;
        val += g_pacc[pidx * HD + d] * w;
    }

    out[(size_t)q * HD + d] = val / L;
}

extern "C" void kernel_launch(void* const* d_in, const int* in_sizes, int n_in,
                              void* d_out, int out_size)
{
    const float* x  = (const float*)d_in[0];
    const float* Wq = (const float*)d_in[1];
    const float* Wk = (const float*)d_in[2];
    const float* Wv = (const float*)d_in[3];
    float* out = (float*)d_out;

    convert_w<<<(3 * HD * DD / 4) / 256, 256>>>(Wq, Wk, Wv);
    qkv_hmma<<<(NTOK / GM_BM) * 3, 256>>>(x);

    dim3 agrid(NCH_MAX, TILES, BB);
    attn_mma<<<agrid, 128>>>();

    combine_kernel<<<(NTOK * HD) / 256, 256>>>(out);
}

// round 7
// speedup vs baseline: 7.7889x; 1.2185x over previous
#include <cuda_runtime.h>
#include <cuda_bf16.h>
#include <math.h>
#include <stdint.h>

#define BB 4
#define TT_SEQ 4096
#define DD 1024
#define HD 64
#define NTOK (BB*TT_SEQ)

#define QT 128
#define CK 256
#define TILES (TT_SEQ/QT)      // 32
#define NCH_MAX (TT_SEQ/CK)    // 16

// Projected Q (pre-scaled by hd^-0.5), K, V. [B*T, HD]
__device__ float g_Q[NTOK*HD];
__device__ float g_K[NTOK*HD];
__device__ float g_V[NTOK*HD];

// W in bf16 hi/lo, rows 0-63=Wq(*0.125), 64-127=Wk, 128-191=Wv
__device__ __nv_bfloat16 g_Whi[3*HD*DD];
__device__ __nv_bfloat16 g_Wlo[3*HD*DD];

// Split-K partials
__device__ float g_pacc[BB*TILES*NCH_MAX*QT*HD];
__device__ float g_pm  [BB*TILES*NCH_MAX*QT];
__device__ float g_pl  [BB*TILES*NCH_MAX*QT];

__device__ __forceinline__ uint32_t pack_bf16(float a, float b) {
    __nv_bfloat162 t = __floats2bfloat162_rn(a, b);
    return *reinterpret_cast<uint32_t*>(&t);
}

__device__ __forceinline__ void split2(float a, float b, uint32_t& hi, uint32_t& lo) {
    __nv_bfloat162 h = __floats2bfloat162_rn(a, b);
    hi = *reinterpret_cast<uint32_t*>(&h);
    lo = pack_bf16(a - __bfloat162float(h.x), b - __bfloat162float(h.y));
}

__device__ __forceinline__ void mma16816(float* d, const uint32_t* a, const uint32_t* b) {
    asm volatile(
        "mma.sync.aligned.m16n8k16.row.col.f32.bf16.bf16.f32 "
        "{%0,%1,%2,%3}, {%4,%5,%6,%7}, {%8,%9}, {%0,%1,%2,%3};"
        : "+f"(d[0]), "+f"(d[1]), "+f"(d[2]), "+f"(d[3])
        : "r"(a[0]), "r"(a[1]), "r"(a[2]), "r"(a[3]),
          "r"(b[0]), "r"(b[1]));
}

// ldmatrix x4: 4 8x8 b16 matrices, row addresses from lanes
__device__ __forceinline__ void ldsm4(uint32_t* d, uint32_t addr) {
    asm volatile("ldmatrix.sync.aligned.m8n8.x4.shared.b16 {%0,%1,%2,%3}, [%4];"
        : "=r"(d[0]), "=r"(d[1]), "=r"(d[2]), "=r"(d[3]) : "r"(addr));
}
__device__ __forceinline__ void ldsm4t(uint32_t* d, uint32_t addr) {
    asm volatile("ldmatrix.sync.aligned.m8n8.x4.trans.shared.b16 {%0,%1,%2,%3}, [%4];"
        : "=r"(d[0]), "=r"(d[1]), "=r"(d[2]), "=r"(d[3]) : "r"(addr));
}

// ---------------------------------------------------------------------------
// Kernel 0: convert W (fp32 -> bf16 hi/lo), fold 1/8 into Wq.
// ---------------------------------------------------------------------------
__global__ __launch_bounds__(256) void convert_w(
    const float* __restrict__ Wq,
    const float* __restrict__ Wk,
    const float* __restrict__ Wv)
{
    const int idx = blockIdx.x * 256 + threadIdx.x;
    const int e0  = idx * 4;
    const int row = e0 >> 10;
    const int col = e0 & 1023;
    const float* src = (row < 64) ? Wq + (size_t)row * DD
                     : (row < 128) ? Wk + (size_t)(row - 64) * DD
                                   : Wv + (size_t)(row - 128) * DD;
    const float sc = (row < 64) ? 0.125f : 1.0f;
    float4 v = *(const float4*)(src + col);
    v.x *= sc; v.y *= sc; v.z *= sc; v.w *= sc;

    uint2 hi, lo;
    split2(v.x, v.y, hi.x, lo.x);
    split2(v.z, v.w, hi.y, lo.y);

    *(uint2*)(g_Whi + e0) = hi;
    *(uint2*)(g_Wlo + e0) = lo;
}

// ---------------------------------------------------------------------------
// Kernel 1: QKV projection via mma.sync (bf16 hi/lo split). Unchanged from R5.
// ---------------------------------------------------------------------------
#define GM_BM 128
#define GM_BN 64
#define GM_BK 32
#define XLD 40
#define WLD 40

__global__ __launch_bounds__(256) void qkv_hmma(const float* __restrict__ x)
{
    __shared__ __nv_bfloat16 xhi[GM_BM * XLD];
    __shared__ __nv_bfloat16 xlo[GM_BM * XLD];
    __shared__ __nv_bfloat16 whi[GM_BN * WLD];
    __shared__ __nv_bfloat16 wlo[GM_BN * WLD];

    const int nblk = blockIdx.x % 3;
    const int m0   = (blockIdx.x / 3) * GM_BM;

    const int tid  = threadIdx.x;
    const int warp = tid >> 5;
    const int lane = tid & 31;
    const int wm   = (warp & 3) * 32;
    const int wn   = (warp >> 2) * 32;
    const int g    = lane >> 2;
    const int t4   = lane & 3;

    float acc[2][4][4];
    #pragma unroll
    for (int mi = 0; mi < 2; mi++)
        #pragma unroll
        for (int ni = 0; ni < 4; ni++)
            #pragma unroll
            for (int k = 0; k < 4; k++) acc[mi][ni][k] = 0.f;

    const int xr = tid >> 1;
    const int xp = tid & 1;

    for (int k0 = 0; k0 < DD; k0 += GM_BK) {
        __syncthreads();
        {
            const float4* src = (const float4*)(x + (size_t)(m0 + xr) * DD + k0 + xp * 16);
            #pragma unroll
            for (int i = 0; i < 4; i++) {
                float4 v = src[i];
                const int o = xr * XLD + xp * 16 + i * 4;
                uint32_t h0, l0, h1, l1;
                split2(v.x, v.y, h0, l0);
                split2(v.z, v.w, h1, l1);
                *(uint32_t*)(xhi + o + 0) = h0;
                *(uint32_t*)(xhi + o + 2) = h1;
                *(uint32_t*)(xlo + o + 0) = l0;
                *(uint32_t*)(xlo + o + 2) = l1;
            }
        }
        {
            const int wr = tid >> 2;
            const int wc = (tid & 3) * 8;
            const size_t gof = (size_t)(nblk * 64 + wr) * DD + k0 + wc;
            *(uint4*)(whi + wr * WLD + wc) = *(const uint4*)(g_Whi + gof);
            *(uint4*)(wlo + wr * WLD + wc) = *(const uint4*)(g_Wlo + gof);
        }
        __syncthreads();

        #pragma unroll
        for (int kk = 0; kk < GM_BK; kk += 16) {
            uint32_t ahi[2][4], alo[2][4], bhi[4][2], blo[4][2];
            #pragma unroll
            for (int mi = 0; mi < 2; mi++) {
                const int rb = wm + mi * 16 + g;
                const int cb = kk + 2 * t4;
                ahi[mi][0] = *(const uint32_t*)(xhi + rb * XLD + cb);
                ahi[mi][1] = *(const uint32_t*)(xhi + (rb + 8) * XLD + cb);
                ahi[mi][2] = *(const uint32_t*)(xhi + rb * XLD + cb + 8);
                ahi[mi][3] = *(const uint32_t*)(xhi + (rb + 8) * XLD + cb + 8);
            }
            #pragma unroll
            for (int ni = 0; ni < 4; ni++) {
                const int nr = wn + ni * 8 + g;
                const int cb = kk + 2 * t4;
                bhi[ni][0] = *(const uint32_t*)(whi + nr * WLD + cb);
                bhi[ni][1] = *(const uint32_t*)(whi + nr * WLD + cb + 8);
            }
            #pragma unroll
            for (int mi = 0; mi < 2; mi++)
                #pragma unroll
                for (int ni = 0; ni < 4; ni++)
                    mma16816(acc[mi][ni], ahi[mi], bhi[ni]);
            #pragma unroll
            for (int ni = 0; ni < 4; ni++) {
                const int nr = wn + ni * 8 + g;
                const int cb = kk + 2 * t4;
                blo[ni][0] = *(const uint32_t*)(wlo + nr * WLD + cb);
                blo[ni][1] = *(const uint32_t*)(wlo + nr * WLD + cb + 8);
            }
            #pragma unroll
            for (int mi = 0; mi < 2; mi++)
                #pragma unroll
                for (int ni = 0; ni < 4; ni++)
                    mma16816(acc[mi][ni], ahi[mi], blo[ni]);
            #pragma unroll
            for (int mi = 0; mi < 2; mi++) {
                const int rb = wm + mi * 16 + g;
                const int cb = kk + 2 * t4;
                alo[mi][0] = *(const uint32_t*)(xlo + rb * XLD + cb);
                alo[mi][1] = *(const uint32_t*)(xlo + (rb + 8) * XLD + cb);
                alo[mi][2] = *(const uint32_t*)(xlo + rb * XLD + cb + 8);
                alo[mi][3] = *(const uint32_t*)(xlo + (rb + 8) * XLD + cb + 8);
            }
            #pragma unroll
            for (int mi = 0; mi < 2; mi++)
                #pragma unroll
                for (int ni = 0; ni < 4; ni++)
                    mma16816(acc[mi][ni], alo[mi], bhi[ni]);
        }
    }

    float* dst = (nblk == 0) ? g_Q : (nblk == 1) ? g_K : g_V;
    #pragma unroll
    for (int mi = 0; mi < 2; mi++) {
        #pragma unroll
        for (int ni = 0; ni < 4; ni++) {
            const size_t r0 = (size_t)m0 + wm + mi * 16 + g;
            const int    c  = wn + ni * 8 + 2 * t4;
            float2 lo2, hi2;
            lo2.x = acc[mi][ni][0]; lo2.y = acc[mi][ni][1];
            hi2.x = acc[mi][ni][2]; hi2.y = acc[mi][ni][3];
            *(float2*)(dst + r0 * HD + c)       = lo2;
            *(float2*)(dst + (r0 + 8) * HD + c) = hi2;
        }
    }
}

// ---------------------------------------------------------------------------
// Kernel 2: split-K causal flash attention on mma.sync + ldmatrix.
// K and V both staged row-major hi/lo (vector stores). B-fragments fetched
// with ldmatrix.x4 (non-trans for K, trans for V), per-lane addresses
// precomputed so loop offsets are constants.
// ---------------------------------------------------------------------------
#define TLD 72

__global__ __launch_bounds__(128) void attn_mma()
{
    __shared__ __nv_bfloat16 khi[64 * TLD];
    __shared__ __nv_bfloat16 klo[64 * TLD];
    __shared__ __nv_bfloat16 vhi[64 * TLD];
    __shared__ __nv_bfloat16 vlo[64 * TLD];

    const int chunk = blockIdx.x;
    const int tile  = blockIdx.y;
    const int b     = blockIdx.z;

    const int kmax = (tile + 1) * QT;
    const int nch  = (kmax + CK - 1) / CK;
    if (chunk >= nch) return;

    const int kstart = chunk * CK;
    const int kend   = min(kstart + CK, kmax);
    const int q0     = tile * QT;

    const int tid  = threadIdx.x;
    const int warp = tid >> 5;
    const int lane = tid & 31;
    const int g    = lane >> 2;
    const int t4   = lane & 3;

    const float* Qb = g_Q + (size_t)b * TT_SEQ * HD;
    const float* Kb = g_K + (size_t)b * TT_SEQ * HD;
    const float* Vb = g_V + (size_t)b * TT_SEQ * HD;

    // per-lane ldmatrix row-address offsets (bytes)
    const int la = lane >> 3;       // matrix index 0..3
    const int lr = lane & 7;        // row within matrix
    // K non-trans: mat a -> (n-group a>>1, k-colhalf a&1)
    const uint32_t k_lane_off = (uint32_t)((((la >> 1) * 8 + lr) * TLD + (la & 1) * 8) * 2);
    // V trans: mat a -> (key-half a&1, n-group a>>1)
    const uint32_t v_lane_off = (uint32_t)((((la & 1) * 8 + lr) * TLD + (la >> 1) * 8) * 2);

    const uint32_t khi_s = (uint32_t)__cvta_generic_to_shared(khi) + k_lane_off;
    const uint32_t klo_s = (uint32_t)__cvta_generic_to_shared(klo) + k_lane_off;
    const uint32_t vhi_s = (uint32_t)__cvta_generic_to_shared(vhi) + v_lane_off;
    const uint32_t vlo_s = (uint32_t)__cvta_generic_to_shared(vlo) + v_lane_off;

    // ---- Q fragments: load once from global, split hi/lo ----
    uint32_t Qh[2][4][4], Ql[2][4][4];
    #pragma unroll
    for (int mi = 0; mi < 2; mi++) {
        const int ar = q0 + warp * 32 + mi * 16 + g;
        const float* r0 = Qb + (size_t)ar * HD;
        const float* r1 = r0 + 8 * HD;
        #pragma unroll
        for (int ks = 0; ks < 4; ks++) {
            const int c = ks * 16 + 2 * t4;
            float2 v00 = *(const float2*)(r0 + c);
            float2 v10 = *(const float2*)(r1 + c);
            float2 v01 = *(const float2*)(r0 + c + 8);
            float2 v11 = *(const float2*)(r1 + c + 8);
            split2(v00.x, v00.y, Qh[mi][ks][0], Ql[mi][ks][0]);
            split2(v10.x, v10.y, Qh[mi][ks][1], Ql[mi][ks][1]);
            split2(v01.x, v01.y, Qh[mi][ks][2], Ql[mi][ks][2]);
            split2(v11.x, v11.y, Qh[mi][ks][3], Ql[mi][ks][3]);
        }
    }

    float o[2][8][4];
    #pragma unroll
    for (int mi = 0; mi < 2; mi++)
        #pragma unroll
        for (int ni = 0; ni < 8; ni++)
            #pragma unroll
            for (int e = 0; e < 4; e++) o[mi][ni][e] = 0.f;
    float m_[2][2] = {{-1e20f, -1e20f}, {-1e20f, -1e20f}};
    float l_[2][2] = {{0.f, 0.f}, {0.f, 0.f}};

    for (int k0 = kstart; k0 < kend; k0 += 64) {
        __syncthreads();
        // ---- stage K and V row-major hi/lo ----
        {
            const int row  = tid >> 1;
            const int half = (tid & 1) * 32;
            const float4* ksrc = (const float4*)(Kb + (size_t)(k0 + row) * HD + half);
            const float4* vsrc = (const float4*)(Vb + (size_t)(k0 + row) * HD + half);
            #pragma unroll
            for (int i = 0; i < 8; i++) {
                float4 v = ksrc[i];
                uint32_t h0, l0, h1, l1;
                split2(v.x, v.y, h0, l0);
                split2(v.z, v.w, h1, l1);
                const int off = row * TLD + half + i * 4;
                *(uint32_t*)(khi + off + 0) = h0;
                *(uint32_t*)(khi + off + 2) = h1;
                *(uint32_t*)(klo + off + 0) = l0;
                *(uint32_t*)(klo + off + 2) = l1;
            }
            #pragma unroll
            for (int i = 0; i < 8; i++) {
                float4 v = vsrc[i];
                uint32_t h0, l0, h1, l1;
                split2(v.x, v.y, h0, l0);
                split2(v.z, v.w, h1, l1);
                const int off = row * TLD + half + i * 4;
                *(uint32_t*)(vhi + off + 0) = h0;
                *(uint32_t*)(vhi + off + 2) = h1;
                *(uint32_t*)(vlo + off + 0) = l0;
                *(uint32_t*)(vlo + off + 2) = l1;
            }
        }
        __syncthreads();

        #pragma unroll
        for (int mi = 0; mi < 2; mi++) {
            const int rbase = warp * 32 + mi * 16;

            // ---- S = Q K^T ----
            float s[8][4];
            #pragma unroll
            for (int ni = 0; ni < 8; ni++)
                #pragma unroll
                for (int e = 0; e < 4; e++) s[ni][e] = 0.f;

            #pragma unroll
            for (int ks = 0; ks < 4; ks++) {
                #pragma unroll
                for (int p = 0; p < 4; p++) {   // n-group pairs
                    const uint32_t off = (uint32_t)(p * (16 * TLD * 2) + ks * 32);
                    uint32_t bh[4], bl[4];
                    ldsm4(bh, khi_s + off);
                    ldsm4(bl, klo_s + off);
                    mma16816(s[2*p],   Qh[mi][ks], bh);
                    mma16816(s[2*p],   Qh[mi][ks], bl);
                    mma16816(s[2*p],   Ql[mi][ks], bh);
                    mma16816(s[2*p+1], Qh[mi][ks], bh + 2);
                    mma16816(s[2*p+1], Qh[mi][ks], bl + 2);
                    mma16816(s[2*p+1], Ql[mi][ks], bh + 2);
                }
            }

            // ---- causal mask ----
            if (k0 + 63 > q0 + rbase) {
                const int qa = q0 + rbase + g;
                #pragma unroll
                for (int ni = 0; ni < 8; ni++) {
                    const int kc = k0 + ni * 8 + 2 * t4;
                    if (kc     > qa)     s[ni][0] = -1e30f;
                    if (kc + 1 > qa)     s[ni][1] = -1e30f;
                    if (kc     > qa + 8) s[ni][2] = -1e30f;
                    if (kc + 1 > qa + 8) s[ni][3] = -1e30f;
                }
            }

            // ---- online softmax ----
            float mxA = -1e30f, mxB = -1e30f;
            #pragma unroll
            for (int ni = 0; ni < 8; ni++) {
                mxA = fmaxf(mxA, fmaxf(s[ni][0], s[ni][1]));
                mxB = fmaxf(mxB, fmaxf(s[ni][2], s[ni][3]));
            }
            mxA = fmaxf(mxA, __shfl_xor_sync(0xffffffffu, mxA, 1));
            mxA = fmaxf(mxA, __shfl_xor_sync(0xffffffffu, mxA, 2));
            mxB = fmaxf(mxB, __shfl_xor_sync(0xffffffffu, mxB, 1));
            mxB = fmaxf(mxB, __shfl_xor_sync(0xffffffffu, mxB, 2));

            const float mA = fmaxf(m_[mi][0], mxA);
            const float mB = fmaxf(m_[mi][1], mxB);
            const float scA = __expf(m_[mi][0] - mA);
            const float scB = __expf(m_[mi][1] - mB);
            m_[mi][0] = mA; m_[mi][1] = mB;

            uint32_t Ph[4][4], Pl[4][4];
            float sA = 0.f, sB = 0.f;
            #pragma unroll
            for (int ni = 0; ni < 8; ni++) {
                float p0 = __expf(s[ni][0] - mA);
                float p1 = __expf(s[ni][1] - mA);
                float p2 = __expf(s[ni][2] - mB);
                float p3 = __expf(s[ni][3] - mB);
                sA += p0 + p1; sB += p2 + p3;
                const int ks   = ni >> 1;
                const int base = (ni & 1) * 2;
                split2(p0, p1, Ph[ks][base + 0], Pl[ks][base + 0]);
                split2(p2, p3, Ph[ks][base + 1], Pl[ks][base + 1]);
            }
            sA += __shfl_xor_sync(0xffffffffu, sA, 1);
            sA += __shfl_xor_sync(0xffffffffu, sA, 2);
            sB += __shfl_xor_sync(0xffffffffu, sB, 1);
            sB += __shfl_xor_sync(0xffffffffu, sB, 2);
            l_[mi][0] = l_[mi][0] * scA + sA;
            l_[mi][1] = l_[mi][1] * scB + sB;

            #pragma unroll
            for (int ni = 0; ni < 8; ni++) {
                o[mi][ni][0] *= scA; o[mi][ni][1] *= scA;
                o[mi][ni][2] *= scB; o[mi][ni][3] *= scB;
            }

            // ---- O += P V ----
            #pragma unroll
            for (int ks = 0; ks < 4; ks++) {       // key window
                #pragma unroll
                for (int p = 0; p < 4; p++) {      // n-group pairs (hd)
                    const uint32_t off = (uint32_t)(ks * (16 * TLD * 2) + p * 32);
                    uint32_t bh[4], bl[4];
                    ldsm4t(bh, vhi_s + off);
                    ldsm4t(bl, vlo_s + off);
                    mma16816(o[mi][2*p],   Ph[ks], bh);
                    mma16816(o[mi][2*p],   Ph[ks], bl);
                    mma16816(o[mi][2*p],   Pl[ks], bh);
                    mma16816(o[mi][2*p+1], Ph[ks], bh + 2);
                    mma16816(o[mi][2*p+1], Ph[ks], bl + 2);
                    mma16816(o[mi][2*p+1], Pl[ks], bh + 2);
                }
            }
        }
    }

    // ---- write partials ----
    const size_t pbase = ((size_t)(b * TILES + tile) * NCH_MAX + chunk) * QT;
    #pragma unroll
    for (int mi = 0; mi < 2; mi++) {
        const int lrA = warp * 32 + mi * 16 + g;
        if (t4 == 0) {
            g_pm[pbase + lrA]     = m_[mi][0];
            g_pl[pbase + lrA]     = l_[mi][0];
            g_pm[pbase + lrA + 8] = m_[mi][1];
            g_pl[pbase + lrA + 8] = l_[mi][1];
        }
        #pragma unroll
        for (int ni = 0; ni < 8; ni++) {
            const int c = ni * 8 + 2 * t4;
            float2 vA, vB;
            vA.x = o[mi][ni][0]; vA.y = o[mi][ni][1];
            vB.x = o[mi][ni][2]; vB.y = o[mi][ni][3];
            *(float2*)(g_pacc + (pbase + lrA) * HD + c)       = vA;
            *(float2*)(g_pacc + (pbase + lrA + 8) * HD + c)   = vB;
        }
    }
}

// ---------------------------------------------------------------------------
// Kernel 3: combine split-K partials, float4 vectorized.
// ---------------------------------------------------------------------------
__global__ __launch_bounds__(256) void combine_kernel(float* __restrict__ out)
{
    const int gid = blockIdx.x * 256 + threadIdx.x;   // over NTOK*16
    const int q   = gid >> 4;
    const int d   = (gid & 15) * 4;

    const int b      = q / TT_SEQ;
    const int t_in_b = q % TT_SEQ;
    const int tile   = t_in_b / QT;
    const int qi     = t_in_b % QT;

    const int kmax = (tile + 1) * QT;
    const int nch  = (kmax + CK - 1) / CK;

    const size_t base = ((size_t)(b * TILES + tile) * NCH_MAX) * QT + qi;

    float mstar = -1e30f;
    for (int i = 0; i < nch; i++) {
        float mi = g_pm[base + (size_t)i * QT];
        mstar = fmaxf(mstar, mi);
    }

    float L = 0.f;
    float4 val = make_float4(0.f, 0.f, 0.f, 0.f);
    for (int i = 0; i < nch; i++) {
        const size_t pidx = base + (size_t)i * QT;
        float w = __expf(g_pm[pidx] - mstar);
        L += g_pl[pidx] * w;
        float4 a = *(const float4*)(g_pacc + pidx * HD + d);
        val.x += a.x * w; val.y += a.y * w;
        val.z += a.z * w; val.w += a.w * w;
    }

    const float inv = 1.f / L;
    float4 r;
    r.x = val.x * inv; r.y = val.y * inv; r.z = val.z * inv; r.w = val.w * inv;
    *(float4*)(out + (size_t)q * HD + d) = r;
}

extern "C" void kernel_launch(void* const* d_in, const int* in_sizes, int n_in,
                              void* d_out, int out_size)
{
    const float* x  = (const float*)d_in[0];
    const float* Wq = (const float*)d_in[1];
    const float* Wk = (const float*)d_in[2];
    const float* Wv = (const float*)d_in[3];
    float* out = (float*)d_out;

    convert_w<<<(3 * HD * DD / 4) / 256, 256>>>(Wq, Wk, Wv);
    qkv_hmma<<<(NTOK / GM_BM) * 3, 256>>>(x);

    dim3 agrid(NCH_MAX, TILES, BB);
    attn_mma<<<agrid, 128>>>();

    combine_kernel<<<(NTOK * 16) / 256, 256>>>(out);
}

// round 8
// speedup vs baseline: 8.6150x; 1.1061x over previous
#include <cuda_runtime.h>
#include <cuda_bf16.h>
#include <math.h>
#include <stdint.h>

#define BB 4
#define TT_SEQ 4096
#define DD 1024
#define HD 64
#define NTOK (BB*TT_SEQ)

#define QT 128
#define CK 256
#define TILES (TT_SEQ/QT)      // 32
#define NCH_MAX (TT_SEQ/CK)    // 16

// Q/K/V stored ONLY as packed bf16 hi/lo (pair-packed uint32 at even cols).
// Q pre-scaled by hd^-0.5.
__device__ __nv_bfloat16 g_Qhi[NTOK*HD];
__device__ __nv_bfloat16 g_Qlo[NTOK*HD];
__device__ __nv_bfloat16 g_Khi[NTOK*HD];
__device__ __nv_bfloat16 g_Klo[NTOK*HD];
__device__ __nv_bfloat16 g_Vhi[NTOK*HD];
__device__ __nv_bfloat16 g_Vlo[NTOK*HD];

// W in bf16 hi/lo, rows 0-63=Wq(*0.125), 64-127=Wk, 128-191=Wv
__device__ __nv_bfloat16 g_Whi[3*HD*DD];
__device__ __nv_bfloat16 g_Wlo[3*HD*DD];

// Split-K partials
__device__ float g_pacc[BB*TILES*NCH_MAX*QT*HD];
__device__ float g_pm  [BB*TILES*NCH_MAX*QT];
__device__ float g_pl  [BB*TILES*NCH_MAX*QT];

__device__ __forceinline__ uint32_t pack_bf16(float a, float b) {
    __nv_bfloat162 t = __floats2bfloat162_rn(a, b);
    return *reinterpret_cast<uint32_t*>(&t);
}

__device__ __forceinline__ void split2(float a, float b, uint32_t& hi, uint32_t& lo) {
    __nv_bfloat162 h = __floats2bfloat162_rn(a, b);
    hi = *reinterpret_cast<uint32_t*>(&h);
    lo = pack_bf16(a - __bfloat162float(h.x), b - __bfloat162float(h.y));
}

__device__ __forceinline__ void mma16816(float* d, const uint32_t* a, const uint32_t* b) {
    asm volatile(
        "mma.sync.aligned.m16n8k16.row.col.f32.bf16.bf16.f32 "
        "{%0,%1,%2,%3}, {%4,%5,%6,%7}, {%8,%9}, {%0,%1,%2,%3};"
        : "+f"(d[0]), "+f"(d[1]), "+f"(d[2]), "+f"(d[3])
        : "r"(a[0]), "r"(a[1]), "r"(a[2]), "r"(a[3]),
          "r"(b[0]), "r"(b[1]));
}

__device__ __forceinline__ void ldsm4(uint32_t* d, uint32_t addr) {
    asm volatile("ldmatrix.sync.aligned.m8n8.x4.shared.b16 {%0,%1,%2,%3}, [%4];"
        : "=r"(d[0]), "=r"(d[1]), "=r"(d[2]), "=r"(d[3]) : "r"(addr));
}
__device__ __forceinline__ void ldsm4t(uint32_t* d, uint32_t addr) {
    asm volatile("ldmatrix.sync.aligned.m8n8.x4.trans.shared.b16 {%0,%1,%2,%3}, [%4];"
        : "=r"(d[0]), "=r"(d[1]), "=r"(d[2]), "=r"(d[3]) : "r"(addr));
}

// ---------------------------------------------------------------------------
// Kernel 0: convert W (fp32 -> bf16 hi/lo), fold 1/8 into Wq.
// ---------------------------------------------------------------------------
__global__ __launch_bounds__(256) void convert_w(
    const float* __restrict__ Wq,
    const float* __restrict__ Wk,
    const float* __restrict__ Wv)
{
    const int idx = blockIdx.x * 256 + threadIdx.x;
    const int e0  = idx * 4;
    const int row = e0 >> 10;
    const int col = e0 & 1023;
    const float* src = (row < 64) ? Wq + (size_t)row * DD
                     : (row < 128) ? Wk + (size_t)(row - 64) * DD
                                   : Wv + (size_t)(row - 128) * DD;
    const float sc = (row < 64) ? 0.125f : 1.0f;
    float4 v = *(const float4*)(src + col);
    v.x *= sc; v.y *= sc; v.z *= sc; v.w *= sc;

    uint2 hi, lo;
    split2(v.x, v.y, hi.x, lo.x);
    split2(v.z, v.w, hi.y, lo.y);

    *(uint2*)(g_Whi + e0) = hi;
    *(uint2*)(g_Wlo + e0) = lo;
}

// ---------------------------------------------------------------------------
// Kernel 1: QKV projection via mma.sync (bf16 hi/lo split).
// Epilogue writes packed bf16 hi/lo pairs (mma operand format) directly.
// ---------------------------------------------------------------------------
#define GM_BM 128
#define GM_BN 64
#define GM_BK 32
#define XLD 40
#define WLD 40

__global__ __launch_bounds__(256) void qkv_hmma(const float* __restrict__ x)
{
    __shared__ __nv_bfloat16 xhi[GM_BM * XLD];
    __shared__ __nv_bfloat16 xlo[GM_BM * XLD];
    __shared__ __nv_bfloat16 whi[GM_BN * WLD];
    __shared__ __nv_bfloat16 wlo[GM_BN * WLD];

    const int nblk = blockIdx.x % 3;
    const int m0   = (blockIdx.x / 3) * GM_BM;

    const int tid  = threadIdx.x;
    const int warp = tid >> 5;
    const int lane = tid & 31;
    const int wm   = (warp & 3) * 32;
    const int wn   = (warp >> 2) * 32;
    const int g    = lane >> 2;
    const int t4   = lane & 3;

    float acc[2][4][4];
    #pragma unroll
    for (int mi = 0; mi < 2; mi++)
        #pragma unroll
        for (int ni = 0; ni < 4; ni++)
            #pragma unroll
            for (int k = 0; k < 4; k++) acc[mi][ni][k] = 0.f;

    const int xr = tid >> 1;
    const int xp = tid & 1;

    for (int k0 = 0; k0 < DD; k0 += GM_BK) {
        __syncthreads();
        {
            const float4* src = (const float4*)(x + (size_t)(m0 + xr) * DD + k0 + xp * 16);
            #pragma unroll
            for (int i = 0; i < 4; i++) {
                float4 v = src[i];
                const int o = xr * XLD + xp * 16 + i * 4;
                uint32_t h0, l0, h1, l1;
                split2(v.x, v.y, h0, l0);
                split2(v.z, v.w, h1, l1);
                *(uint32_t*)(xhi + o + 0) = h0;
                *(uint32_t*)(xhi + o + 2) = h1;
                *(uint32_t*)(xlo + o + 0) = l0;
                *(uint32_t*)(xlo + o + 2) = l1;
            }
        }
        {
            const int wr = tid >> 2;
            const int wc = (tid & 3) * 8;
            const size_t gof = (size_t)(nblk * 64 + wr) * DD + k0 + wc;
            *(uint4*)(whi + wr * WLD + wc) = *(const uint4*)(g_Whi + gof);
            *(uint4*)(wlo + wr * WLD + wc) = *(const uint4*)(g_Wlo + gof);
        }
        __syncthreads();

        #pragma unroll
        for (int kk = 0; kk < GM_BK; kk += 16) {
            uint32_t ahi[2][4], alo[2][4], bhi[4][2], blo[4][2];
            #pragma unroll
            for (int mi = 0; mi < 2; mi++) {
                const int rb = wm + mi * 16 + g;
                const int cb = kk + 2 * t4;
                ahi[mi][0] = *(const uint32_t*)(xhi + rb * XLD + cb);
                ahi[mi][1] = *(const uint32_t*)(xhi + (rb + 8) * XLD + cb);
                ahi[mi][2] = *(const uint32_t*)(xhi + rb * XLD + cb + 8);
                ahi[mi][3] = *(const uint32_t*)(xhi + (rb + 8) * XLD + cb + 8);
            }
            #pragma unroll
            for (int ni = 0; ni < 4; ni++) {
                const int nr = wn + ni * 8 + g;
                const int cb = kk + 2 * t4;
                bhi[ni][0] = *(const uint32_t*)(whi + nr * WLD + cb);
                bhi[ni][1] = *(const uint32_t*)(whi + nr * WLD + cb + 8);
            }
            #pragma unroll
            for (int mi = 0; mi < 2; mi++)
                #pragma unroll
                for (int ni = 0; ni < 4; ni++)
                    mma16816(acc[mi][ni], ahi[mi], bhi[ni]);
            #pragma unroll
            for (int ni = 0; ni < 4; ni++) {
                const int nr = wn + ni * 8 + g;
                const int cb = kk + 2 * t4;
                blo[ni][0] = *(const uint32_t*)(wlo + nr * WLD + cb);
                blo[ni][1] = *(const uint32_t*)(wlo + nr * WLD + cb + 8);
            }
            #pragma unroll
            for (int mi = 0; mi < 2; mi++)
                #pragma unroll
                for (int ni = 0; ni < 4; ni++)
                    mma16816(acc[mi][ni], ahi[mi], blo[ni]);
            #pragma unroll
            for (int mi = 0; mi < 2; mi++) {
                const int rb = wm + mi * 16 + g;
                const int cb = kk + 2 * t4;
                alo[mi][0] = *(const uint32_t*)(xlo + rb * XLD + cb);
                alo[mi][1] = *(const uint32_t*)(xlo + (rb + 8) * XLD + cb);
                alo[mi][2] = *(const uint32_t*)(xlo + rb * XLD + cb + 8);
                alo[mi][3] = *(const uint32_t*)(xlo + (rb + 8) * XLD + cb + 8);
            }
            #pragma unroll
            for (int mi = 0; mi < 2; mi++)
                #pragma unroll
                for (int ni = 0; ni < 4; ni++)
                    mma16816(acc[mi][ni], alo[mi], bhi[ni]);
        }
    }

    __nv_bfloat16* dhi = (nblk == 0) ? g_Qhi : (nblk == 1) ? g_Khi : g_Vhi;
    __nv_bfloat16* dlo = (nblk == 0) ? g_Qlo : (nblk == 1) ? g_Klo : g_Vlo;
    #pragma unroll
    for (int mi = 0; mi < 2; mi++) {
        #pragma unroll
        for (int ni = 0; ni < 4; ni++) {
            const size_t r0 = (size_t)m0 + wm + mi * 16 + g;
            const int    c  = wn + ni * 8 + 2 * t4;
            uint32_t h, l;
            split2(acc[mi][ni][0], acc[mi][ni][1], h, l);
            *(uint32_t*)(dhi + r0 * HD + c) = h;
            *(uint32_t*)(dlo + r0 * HD + c) = l;
            split2(acc[mi][ni][2], acc[mi][ni][3], h, l);
            *(uint32_t*)(dhi + (r0 + 8) * HD + c) = h;
            *(uint32_t*)(dlo + (r0 + 8) * HD + c) = l;
        }
    }
}

// ---------------------------------------------------------------------------
// Kernel 2: split-K causal flash attention on mma.sync + ldmatrix.
// K/V/Q pre-split to bf16 hi/lo in global: staging is pure uint4 copies,
// Q fragments are direct uint32 loads.
// ---------------------------------------------------------------------------
#define TLD 72

__global__ __launch_bounds__(128) void attn_mma()
{
    __shared__ __nv_bfloat16 khi[64 * TLD];
    __shared__ __nv_bfloat16 klo[64 * TLD];
    __shared__ __nv_bfloat16 vhi[64 * TLD];
    __shared__ __nv_bfloat16 vlo[64 * TLD];

    const int chunk = blockIdx.x;
    const int tile  = blockIdx.y;
    const int b     = blockIdx.z;

    const int kmax = (tile + 1) * QT;
    const int nch  = (kmax + CK - 1) / CK;
    if (chunk >= nch) return;

    const int kstart = chunk * CK;
    const int kend   = min(kstart + CK, kmax);
    const int q0     = tile * QT;

    const int tid  = threadIdx.x;
    const int warp = tid >> 5;
    const int lane = tid & 31;
    const int g    = lane >> 2;
    const int t4   = lane & 3;

    const size_t boff = (size_t)b * TT_SEQ * HD;

    // per-lane ldmatrix row-address offsets (bytes)
    const int la = lane >> 3;
    const int lr = lane & 7;
    const uint32_t k_lane_off = (uint32_t)((((la >> 1) * 8 + lr) * TLD + (la & 1) * 8) * 2);
    const uint32_t v_lane_off = (uint32_t)((((la & 1) * 8 + lr) * TLD + (la >> 1) * 8) * 2);

    const uint32_t khi_s = (uint32_t)__cvta_generic_to_shared(khi) + k_lane_off;
    const uint32_t klo_s = (uint32_t)__cvta_generic_to_shared(klo) + k_lane_off;
    const uint32_t vhi_s = (uint32_t)__cvta_generic_to_shared(vhi) + v_lane_off;
    const uint32_t vlo_s = (uint32_t)__cvta_generic_to_shared(vlo) + v_lane_off;

    // ---- Q fragments: direct packed-pair loads ----
    uint32_t Qh[2][4][4], Ql[2][4][4];
    #pragma unroll
    for (int mi = 0; mi < 2; mi++) {
        const size_t ar = boff + (size_t)(q0 + warp * 32 + mi * 16 + g) * HD;
        #pragma unroll
        for (int ks = 0; ks < 4; ks++) {
            const int c = ks * 16 + 2 * t4;
            Qh[mi][ks][0] = *(const uint32_t*)(g_Qhi + ar + c);
            Qh[mi][ks][1] = *(const uint32_t*)(g_Qhi + ar + 8 * HD + c);
            Qh[mi][ks][2] = *(const uint32_t*)(g_Qhi + ar + c + 8);
            Qh[mi][ks][3] = *(const uint32_t*)(g_Qhi + ar + 8 * HD + c + 8);
            Ql[mi][ks][0] = *(const uint32_t*)(g_Qlo + ar + c);
            Ql[mi][ks][1] = *(const uint32_t*)(g_Qlo + ar + 8 * HD + c);
            Ql[mi][ks][2] = *(const uint32_t*)(g_Qlo + ar + c + 8);
            Ql[mi][ks][3] = *(const uint32_t*)(g_Qlo + ar + 8 * HD + c + 8);
        }
    }

    float o[2][8][4];
    #pragma unroll
    for (int mi = 0; mi < 2; mi++)
        #pragma unroll
        for (int ni = 0; ni < 8; ni++)
            #pragma unroll
            for (int e = 0; e < 4; e++) o[mi][ni][e] = 0.f;
    float m_[2][2] = {{-1e20f, -1e20f}, {-1e20f, -1e20f}};
    float l_[2][2] = {{0.f, 0.f}, {0.f, 0.f}};

    for (int k0 = kstart; k0 < kend; k0 += 64) {
        __syncthreads();
        // ---- stage K/V hi/lo: pure uint4 copies (4 per thread per array) ----
        {
            #pragma unroll
            for (int i = 0; i < 4; i++) {
                const int idx = i * 128 + tid;      // 0..511
                const int row = idx >> 3;
                const int seg = (idx & 7) * 8;
                const size_t gsrc = boff + (size_t)(k0 + row) * HD + seg;
                const int    sdst = row * TLD + seg;
                *(uint4*)(khi + sdst) = *(const uint4*)(g_Khi + gsrc);
                *(uint4*)(klo + sdst) = *(const uint4*)(g_Klo + gsrc);
                *(uint4*)(vhi + sdst) = *(const uint4*)(g_Vhi + gsrc);
                *(uint4*)(vlo + sdst) = *(const uint4*)(g_Vlo + gsrc);
            }
        }
        __syncthreads();

        #pragma unroll
        for (int mi = 0; mi < 2; mi++) {
            const int rbase = warp * 32 + mi * 16;

            // ---- S = Q K^T ----
            float s[8][4];
            #pragma unroll
            for (int ni = 0; ni < 8; ni++)
                #pragma unroll
                for (int e = 0; e < 4; e++) s[ni][e] = 0.f;

            #pragma unroll
            for (int ks = 0; ks < 4; ks++) {
                #pragma unroll
                for (int p = 0; p < 4; p++) {
                    const uint32_t off = (uint32_t)(p * (16 * TLD * 2) + ks * 32);
                    uint32_t bh[4], bl[4];
                    ldsm4(bh, khi_s + off);
                    ldsm4(bl, klo_s + off);
                    mma16816(s[2*p],   Qh[mi][ks], bh);
                    mma16816(s[2*p],   Qh[mi][ks], bl);
                    mma16816(s[2*p],   Ql[mi][ks], bh);
                    mma16816(s[2*p+1], Qh[mi][ks], bh + 2);
                    mma16816(s[2*p+1], Qh[mi][ks], bl + 2);
                    mma16816(s[2*p+1], Ql[mi][ks], bh + 2);
                }
            }

            // ---- causal mask ----
            if (k0 + 63 > q0 + rbase) {
                const int qa = q0 + rbase + g;
                #pragma unroll
                for (int ni = 0; ni < 8; ni++) {
                    const int kc = k0 + ni * 8 + 2 * t4;
                    if (kc     > qa)     s[ni][0] = -1e30f;
                    if (kc + 1 > qa)     s[ni][1] = -1e30f;
                    if (kc     > qa + 8) s[ni][2] = -1e30f;
                    if (kc + 1 > qa + 8) s[ni][3] = -1e30f;
                }
            }

            // ---- online softmax ----
            float mxA = -1e30f, mxB = -1e30f;
            #pragma unroll
            for (int ni = 0; ni < 8; ni++) {
                mxA = fmaxf(mxA, fmaxf(s[ni][0], s[ni][1]));
                mxB = fmaxf(mxB, fmaxf(s[ni][2], s[ni][3]));
            }
            mxA = fmaxf(mxA, __shfl_xor_sync(0xffffffffu, mxA, 1));
            mxA = fmaxf(mxA, __shfl_xor_sync(0xffffffffu, mxA, 2));
            mxB = fmaxf(mxB, __shfl_xor_sync(0xffffffffu, mxB, 1));
            mxB = fmaxf(mxB, __shfl_xor_sync(0xffffffffu, mxB, 2));

            const float mA = fmaxf(m_[mi][0], mxA);
            const float mB = fmaxf(m_[mi][1], mxB);
            const float scA = __expf(m_[mi][0] - mA);
            const float scB = __expf(m_[mi][1] - mB);
            m_[mi][0] = mA; m_[mi][1] = mB;

            uint32_t Ph[4][4], Pl[4][4];
            float sA = 0.f, sB = 0.f;
            #pragma unroll
            for (int ni = 0; ni < 8; ni++) {
                float p0 = __expf(s[ni][0] - mA);
                float p1 = __expf(s[ni][1] - mA);
                float p2 = __expf(s[ni][2] - mB);
                float p3 = __expf(s[ni][3] - mB);
                sA += p0 + p1; sB += p2 + p3;
                const int ks   = ni >> 1;
                const int base = (ni & 1) * 2;
                split2(p0, p1, Ph[ks][base + 0], Pl[ks][base + 0]);
                split2(p2, p3, Ph[ks][base + 1], Pl[ks][base + 1]);
            }
            sA += __shfl_xor_sync(0xffffffffu, sA, 1);
            sA += __shfl_xor_sync(0xffffffffu, sA, 2);
            sB += __shfl_xor_sync(0xffffffffu, sB, 1);
            sB += __shfl_xor_sync(0xffffffffu, sB, 2);
            l_[mi][0] = l_[mi][0] * scA + sA;
            l_[mi][1] = l_[mi][1] * scB + sB;

            #pragma unroll
            for (int ni = 0; ni < 8; ni++) {
                o[mi][ni][0] *= scA; o[mi][ni][1] *= scA;
                o[mi][ni][2] *= scB; o[mi][ni][3] *= scB;
            }

            // ---- O += P V ----
            #pragma unroll
            for (int ks = 0; ks < 4; ks++) {
                #pragma unroll
                for (int p = 0; p < 4; p++) {
                    const uint32_t off = (uint32_t)(ks * (16 * TLD * 2) + p * 32);
                    uint32_t bh[4], bl[4];
                    ldsm4t(bh, vhi_s + off);
                    ldsm4t(bl, vlo_s + off);
                    mma16816(o[mi][2*p],   Ph[ks], bh);
                    mma16816(o[mi][2*p],   Ph[ks], bl);
                    mma16816(o[mi][2*p],   Pl[ks], bh);
                    mma16816(o[mi][2*p+1], Ph[ks], bh + 2);
                    mma16816(o[mi][2*p+1], Ph[ks], bl + 2);
                    mma16816(o[mi][2*p+1], Pl[ks], bh + 2);
                }
            }
        }
    }

    // ---- write partials ----
    const size_t pbase = ((size_t)(b * TILES + tile) * NCH_MAX + chunk) * QT;
    #pragma unroll
    for (int mi = 0; mi < 2; mi++) {
        const int lrA = warp * 32 + mi * 16 + g;
        if (t4 == 0) {
            g_pm[pbase + lrA]     = m_[mi][0];
            g_pl[pbase + lrA]     = l_[mi][0];
            g_pm[pbase + lrA + 8] = m_[mi][1];
            g_pl[pbase + lrA + 8] = l_[mi][1];
        }
        #pragma unroll
        for (int ni = 0; ni < 8; ni++) {
            const int c = ni * 8 + 2 * t4;
            float2 vA, vB;
            vA.x = o[mi][ni][0]; vA.y = o[mi][ni][1];
            vB.x = o[mi][ni][2]; vB.y = o[mi][ni][3];
            *(float2*)(g_pacc + (pbase + lrA) * HD + c)       = vA;
            *(float2*)(g_pacc + (pbase + lrA + 8) * HD + c)   = vB;
        }
    }
}

// ---------------------------------------------------------------------------
// Kernel 3: combine split-K partials, float4 vectorized.
// ---------------------------------------------------------------------------
__global__ __launch_bounds__(256) void combine_kernel(float* __restrict__ out)
{
    const int gid = blockIdx.x * 256 + threadIdx.x;
    const int q   = gid >> 4;
    const int d   = (gid & 15) * 4;

    const int b      = q / TT_SEQ;
    const int t_in_b = q % TT_SEQ;
    const int tile   = t_in_b / QT;
    const int qi     = t_in_b % QT;

    const int kmax = (tile + 1) * QT;
    const int nch  = (kmax + CK - 1) / CK;

    const size_t base = ((size_t)(b * TILES + tile) * NCH_MAX) * QT + qi;

    float mstar = -1e30f;
    for (int i = 0; i < nch; i++) {
        float mi = g_pm[base + (size_t)i * QT];
        mstar = fmaxf(mstar, mi);
    }

    float L = 0.f;
    float4 val = make_float4(0.f, 0.f, 0.f, 0.f);
    for (int i = 0; i < nch; i++) {
        const size_t pidx = base + (size_t)i * QT;
        float w = __expf(g_pm[pidx] - mstar);
        L += g_pl[pidx] * w;
        float4 a = *(const float4*)(g_pacc + pidx * HD + d);
        val.x += a.x * w; val.y += a.y * w;
        val.z += a.z * w; val.w += a.w * w;
    }

    const float inv = 1.f / L;
    float4 r;
    r.x = val.x * inv; r.y = val.y * inv; r.z = val.z * inv; r.w = val.w * inv;
    *(float4*)(out + (size_t)q * HD + d) = r;
}

extern "C" void kernel_launch(void* const* d_in, const int* in_sizes, int n_in,
                              void* d_out, int out_size)
{
    const float* x  = (const float*)d_in[0];
    const float* Wq = (const float*)d_in[1];
    const float* Wk = (const float*)d_in[2];
    const float* Wv = (const float*)d_in[3];
    float* out = (float*)d_out;

    convert_w<<<(3 * HD * DD / 4) / 256, 256>>>(Wq, Wk, Wv);
    qkv_hmma<<<(NTOK / GM_BM) * 3, 256>>>(x);

    dim3 agrid(NCH_MAX, TILES, BB);
    attn_mma<<<agrid, 128>>>();

    combine_kernel<<<(NTOK * 16) / 256, 256>>>(out);
}

// round 9
// speedup vs baseline: 9.0139x; 1.0463x over previous
#include <cuda_runtime.h>
#include <cuda_bf16.h>
#include <math.h>
#include <stdint.h>

#define BB 4
#define TT_SEQ 4096
#define DD 1024
#define HD 64
#define NTOK (BB*TT_SEQ)

#define QT 128
#define CK 256
#define TILES (TT_SEQ/QT)      // 32
#define NCH_MAX (TT_SEQ/CK)    // 16

// Q/K/V stored ONLY as packed bf16 hi/lo (pair-packed uint32 at even cols).
// Q pre-scaled by hd^-0.5.
__device__ __nv_bfloat16 g_Qhi[NTOK*HD];
__device__ __nv_bfloat16 g_Qlo[NTOK*HD];
__device__ __nv_bfloat16 g_Khi[NTOK*HD];
__device__ __nv_bfloat16 g_Klo[NTOK*HD];
__device__ __nv_bfloat16 g_Vhi[NTOK*HD];
__device__ __nv_bfloat16 g_Vlo[NTOK*HD];

// W in bf16 hi/lo, rows 0-63=Wq(*0.125), 64-127=Wk, 128-191=Wv
__device__ __nv_bfloat16 g_Whi[3*HD*DD];
__device__ __nv_bfloat16 g_Wlo[3*HD*DD];

// Split-K partials
__device__ float g_pacc[BB*TILES*NCH_MAX*QT*HD];
__device__ float g_pm  [BB*TILES*NCH_MAX*QT];
__device__ float g_pl  [BB*TILES*NCH_MAX*QT];

__device__ __forceinline__ uint32_t pack_bf16(float a, float b) {
    __nv_bfloat162 t = __floats2bfloat162_rn(a, b);
    return *reinterpret_cast<uint32_t*>(&t);
}

__device__ __forceinline__ void split2(float a, float b, uint32_t& hi, uint32_t& lo) {
    __nv_bfloat162 h = __floats2bfloat162_rn(a, b);
    hi = *reinterpret_cast<uint32_t*>(&h);
    lo = pack_bf16(a - __bfloat162float(h.x), b - __bfloat162float(h.y));
}

__device__ __forceinline__ void mma16816(float* d, const uint32_t* a, const uint32_t* b) {
    asm volatile(
        "mma.sync.aligned.m16n8k16.row.col.f32.bf16.bf16.f32 "
        "{%0,%1,%2,%3}, {%4,%5,%6,%7}, {%8,%9}, {%0,%1,%2,%3};"
        : "+f"(d[0]), "+f"(d[1]), "+f"(d[2]), "+f"(d[3])
        : "r"(a[0]), "r"(a[1]), "r"(a[2]), "r"(a[3]),
          "r"(b[0]), "r"(b[1]));
}

__device__ __forceinline__ void ldsm4(uint32_t* d, uint32_t addr) {
    asm volatile("ldmatrix.sync.aligned.m8n8.x4.shared.b16 {%0,%1,%2,%3}, [%4];"
        : "=r"(d[0]), "=r"(d[1]), "=r"(d[2]), "=r"(d[3]) : "r"(addr));
}
__device__ __forceinline__ void ldsm4t(uint32_t* d, uint32_t addr) {
    asm volatile("ldmatrix.sync.aligned.m8n8.x4.trans.shared.b16 {%0,%1,%2,%3}, [%4];"
        : "=r"(d[0]), "=r"(d[1]), "=r"(d[2]), "=r"(d[3]) : "r"(addr));
}

#define CP_ASYNC16(saddr, gptr) \
    asm volatile("cp.async.cg.shared.global [%0], [%1], 16;" :: "r"(saddr), "l"(gptr) : "memory")
#define CP_COMMIT() asm volatile("cp.async.commit_group;" ::: "memory")
#define CP_WAIT0()  asm volatile("cp.async.wait_group 0;" ::: "memory")

// ---------------------------------------------------------------------------
// Kernel 0: convert W (fp32 -> bf16 hi/lo), fold 1/8 into Wq.
// ---------------------------------------------------------------------------
__global__ __launch_bounds__(256) void convert_w(
    const float* __restrict__ Wq,
    const float* __restrict__ Wk,
    const float* __restrict__ Wv)
{
    const int idx = blockIdx.x * 256 + threadIdx.x;
    const int e0  = idx * 4;
    const int row = e0 >> 10;
    const int col = e0 & 1023;
    const float* src = (row < 64) ? Wq + (size_t)row * DD
                     : (row < 128) ? Wk + (size_t)(row - 64) * DD
                                   : Wv + (size_t)(row - 128) * DD;
    const float sc = (row < 64) ? 0.125f : 1.0f;
    float4 v = *(const float4*)(src + col);
    v.x *= sc; v.y *= sc; v.z *= sc; v.w *= sc;

    uint2 hi, lo;
    split2(v.x, v.y, hi.x, lo.x);
    split2(v.z, v.w, hi.y, lo.y);

    *(uint2*)(g_Whi + e0) = hi;
    *(uint2*)(g_Wlo + e0) = lo;
}

// ---------------------------------------------------------------------------
// Kernel 1: QKV projection via mma.sync + ldmatrix fragment loads.
// ---------------------------------------------------------------------------
#define GM_BM 128
#define GM_BN 64
#define GM_BK 32
#define XLD 40
#define WLD 40

__global__ __launch_bounds__(256) void qkv_hmma(const float* __restrict__ x)
{
    __shared__ __nv_bfloat16 xhi[GM_BM * XLD];
    __shared__ __nv_bfloat16 xlo[GM_BM * XLD];
    __shared__ __nv_bfloat16 whi[GM_BN * WLD];
    __shared__ __nv_bfloat16 wlo[GM_BN * WLD];

    const int nblk = blockIdx.x % 3;
    const int m0   = (blockIdx.x / 3) * GM_BM;

    const int tid  = threadIdx.x;
    const int warp = tid >> 5;
    const int lane = tid & 31;
    const int wm   = (warp & 3) * 32;
    const int wn   = (warp >> 2) * 32;
    const int g    = lane >> 2;
    const int t4   = lane & 3;

    // ldmatrix per-lane address offsets (bytes)
    const int la = lane >> 3;
    const int lr = lane & 7;
    // A layout: mat m -> (row-group m&1, k-half m>>1)
    const uint32_t a_off = (uint32_t)((((la & 1) * 8 + lr) * XLD + (la >> 1) * 8) * 2);
    // B layout: mat m -> (n-group m>>1, k-half m&1)
    const uint32_t b_off = (uint32_t)((((la >> 1) * 8 + lr) * WLD + (la & 1) * 8) * 2);

    const uint32_t xhi_s = (uint32_t)__cvta_generic_to_shared(xhi) + (uint32_t)(wm * XLD * 2) + a_off;
    const uint32_t xlo_s = (uint32_t)__cvta_generic_to_shared(xlo) + (uint32_t)(wm * XLD * 2) + a_off;
    const uint32_t whi_s = (uint32_t)__cvta_generic_to_shared(whi) + (uint32_t)(wn * WLD * 2) + b_off;
    const uint32_t wlo_s = (uint32_t)__cvta_generic_to_shared(wlo) + (uint32_t)(wn * WLD * 2) + b_off;

    float acc[2][4][4];
    #pragma unroll
    for (int mi = 0; mi < 2; mi++)
        #pragma unroll
        for (int ni = 0; ni < 4; ni++)
            #pragma unroll
            for (int k = 0; k < 4; k++) acc[mi][ni][k] = 0.f;

    const int xr = tid >> 1;
    const int xp = tid & 1;

    for (int k0 = 0; k0 < DD; k0 += GM_BK) {
        __syncthreads();
        {
            const float4* src = (const float4*)(x + (size_t)(m0 + xr) * DD + k0 + xp * 16);
            #pragma unroll
            for (int i = 0; i < 4; i++) {
                float4 v = src[i];
                const int o = xr * XLD + xp * 16 + i * 4;
                uint32_t h0, l0, h1, l1;
                split2(v.x, v.y, h0, l0);
                split2(v.z, v.w, h1, l1);
                *(uint32_t*)(xhi + o + 0) = h0;
                *(uint32_t*)(xhi + o + 2) = h1;
                *(uint32_t*)(xlo + o + 0) = l0;
                *(uint32_t*)(xlo + o + 2) = l1;
            }
        }
        {
            const int wr = tid >> 2;
            const int wc = (tid & 3) * 8;
            const size_t gof = (size_t)(nblk * 64 + wr) * DD + k0 + wc;
            *(uint4*)(whi + wr * WLD + wc) = *(const uint4*)(g_Whi + gof);
            *(uint4*)(wlo + wr * WLD + wc) = *(const uint4*)(g_Wlo + gof);
        }
        __syncthreads();

        #pragma unroll
        for (int kk = 0; kk < GM_BK; kk += 16) {
            uint32_t ah[2][4], al[2][4], bh[2][4], bl[2][4];
            const uint32_t ko = (uint32_t)(kk * 2);
            ldsm4(ah[0], xhi_s + ko);
            ldsm4(ah[1], xhi_s + (uint32_t)(16 * XLD * 2) + ko);
            ldsm4(al[0], xlo_s + ko);
            ldsm4(al[1], xlo_s + (uint32_t)(16 * XLD * 2) + ko);
            ldsm4(bh[0], whi_s + ko);
            ldsm4(bh[1], whi_s + (uint32_t)(16 * WLD * 2) + ko);
            ldsm4(bl[0], wlo_s + ko);
            ldsm4(bl[1], wlo_s + (uint32_t)(16 * WLD * 2) + ko);

            #pragma unroll
            for (int mi = 0; mi < 2; mi++) {
                #pragma unroll
                for (int nj = 0; nj < 2; nj++) {
                    // hi*hi
                    mma16816(acc[mi][2*nj],   ah[mi], bh[nj]);
                    mma16816(acc[mi][2*nj+1], ah[mi], bh[nj] + 2);
                    // hi*lo
                    mma16816(acc[mi][2*nj],   ah[mi], bl[nj]);
                    mma16816(acc[mi][2*nj+1], ah[mi], bl[nj] + 2);
                    // lo*hi
                    mma16816(acc[mi][2*nj],   al[mi], bh[nj]);
                    mma16816(acc[mi][2*nj+1], al[mi], bh[nj] + 2);
                }
            }
        }
    }

    __nv_bfloat16* dhi = (nblk == 0) ? g_Qhi : (nblk == 1) ? g_Khi : g_Vhi;
    __nv_bfloat16* dlo = (nblk == 0) ? g_Qlo : (nblk == 1) ? g_Klo : g_Vlo;
    #pragma unroll
    for (int mi = 0; mi < 2; mi++) {
        #pragma unroll
        for (int ni = 0; ni < 4; ni++) {
            const size_t r0 = (size_t)m0 + wm + mi * 16 + g;
            const int    c  = wn + ni * 8 + 2 * t4;
            uint32_t h, l;
            split2(acc[mi][ni][0], acc[mi][ni][1], h, l);
            *(uint32_t*)(dhi + r0 * HD + c) = h;
            *(uint32_t*)(dlo + r0 * HD + c) = l;
            split2(acc[mi][ni][2], acc[mi][ni][3], h, l);
            *(uint32_t*)(dhi + (r0 + 8) * HD + c) = h;
            *(uint32_t*)(dlo + (r0 + 8) * HD + c) = l;
        }
    }
}

// ---------------------------------------------------------------------------
// Kernel 2: split-K causal flash attention, cp.async double-buffered.
// Dynamic smem: 2 buffers x (khi|klo|vhi|vlo), each 64xTLD bf16.
// ---------------------------------------------------------------------------
#define TLD 72
#define ARR_B  (64 * TLD * 2)      // 9216 bytes per array
#define BUF_B  (4 * ARR_B)         // 36864 bytes per buffer
#define ATTN_SMEM (2 * BUF_B)      // 73728

__global__ __launch_bounds__(128) void attn_mma()
{
    extern __shared__ char dsm[];

    const int chunk = blockIdx.x;
    const int tile  = blockIdx.y;
    const int b     = blockIdx.z;

    const int kmax = (tile + 1) * QT;
    const int nch  = (kmax + CK - 1) / CK;
    if (chunk >= nch) return;

    const int kstart = chunk * CK;
    const int kend   = min(kstart + CK, kmax);
    const int q0     = tile * QT;

    const int tid  = threadIdx.x;
    const int warp = tid >> 5;
    const int lane = tid & 31;
    const int g    = lane >> 2;
    const int t4   = lane & 3;

    const size_t boff = (size_t)b * TT_SEQ * HD;
    const uint32_t sb = (uint32_t)__cvta_generic_to_shared(dsm);

    // per-lane ldmatrix row-address offsets (bytes)
    const int la = lane >> 3;
    const int lr = lane & 7;
    const uint32_t k_lane_off = (uint32_t)((((la >> 1) * 8 + lr) * TLD + (la & 1) * 8) * 2);
    const uint32_t v_lane_off = (uint32_t)((((la & 1) * 8 + lr) * TLD + (la >> 1) * 8) * 2);

    // staging slots for this thread (2 x uint4 per array)
    const int sr0 = (tid) >> 3,        sg0 = (tid & 7) * 8;          // slot 0
    const int sr1 = (128 + tid) >> 3,  sg1 = (tid & 7) * 8;          // slot 1 (rows 16..)
    // (4 iterations of 128 threads over 512 slots -> unrolled pairs below)

    // ---- Q fragments: direct packed-pair loads ----
    uint32_t Qh[2][4][4], Ql[2][4][4];
    #pragma unroll
    for (int mi = 0; mi < 2; mi++) {
        const size_t ar = boff + (size_t)(q0 + warp * 32 + mi * 16 + g) * HD;
        #pragma unroll
        for (int ks = 0; ks < 4; ks++) {
            const int c = ks * 16 + 2 * t4;
            Qh[mi][ks][0] = *(const uint32_t*)(g_Qhi + ar + c);
            Qh[mi][ks][1] = *(const uint32_t*)(g_Qhi + ar + 8 * HD + c);
            Qh[mi][ks][2] = *(const uint32_t*)(g_Qhi + ar + c + 8);
            Qh[mi][ks][3] = *(const uint32_t*)(g_Qhi + ar + 8 * HD + c + 8);
            Ql[mi][ks][0] = *(const uint32_t*)(g_Qlo + ar + c);
            Ql[mi][ks][1] = *(const uint32_t*)(g_Qlo + ar + 8 * HD + c);
            Ql[mi][ks][2] = *(const uint32_t*)(g_Qlo + ar + c + 8);
            Ql[mi][ks][3] = *(const uint32_t*)(g_Qlo + ar + 8 * HD + c + 8);
        }
    }

    float o[2][8][4];
    #pragma unroll
    for (int mi = 0; mi < 2; mi++)
        #pragma unroll
        for (int ni = 0; ni < 8; ni++)
            #pragma unroll
            for (int e = 0; e < 4; e++) o[mi][ni][e] = 0.f;
    float m_[2][2] = {{-1e20f, -1e20f}, {-1e20f, -1e20f}};
    float l_[2][2] = {{0.f, 0.f}, {0.f, 0.f}};

    // ---- stage helper (macro-expanded inline) ----
    auto stage_tile = [&](uint32_t sbase, int k0) {
        #pragma unroll
        for (int i = 0; i < 4; i++) {
            const int idx = i * 128 + tid;
            const int row = idx >> 3;
            const int seg = (idx & 7) * 8;
            const size_t gsrc = boff + (size_t)(k0 + row) * HD + seg;
            const uint32_t sdst = sbase + (uint32_t)((row * TLD + seg) * 2);
            CP_ASYNC16(sdst + 0 * ARR_B, g_Khi + gsrc);
            CP_ASYNC16(sdst + 1 * ARR_B, g_Klo + gsrc);
            CP_ASYNC16(sdst + 2 * ARR_B, g_Vhi + gsrc);
            CP_ASYNC16(sdst + 3 * ARR_B, g_Vlo + gsrc);
        }
    };

    stage_tile(sb, kstart);
    CP_COMMIT();

    int cur = 0;
    for (int k0 = kstart; k0 < kend; k0 += 64) {
        CP_WAIT0();
        __syncthreads();
        if (k0 + 64 < kend) {
            stage_tile(sb + (uint32_t)((cur ^ 1) * BUF_B), k0 + 64);
            CP_COMMIT();
        }

        const uint32_t bufb  = sb + (uint32_t)(cur * BUF_B);
        const uint32_t khi_s = bufb + 0 * ARR_B + k_lane_off;
        const uint32_t klo_s = bufb + 1 * ARR_B + k_lane_off;
        const uint32_t vhi_s = bufb + 2 * ARR_B + v_lane_off;
        const uint32_t vlo_s = bufb + 3 * ARR_B + v_lane_off;

        #pragma unroll
        for (int mi = 0; mi < 2; mi++) {
            const int rbase = warp * 32 + mi * 16;

            // ---- S = Q K^T ----
            float s[8][4];
            #pragma unroll
            for (int ni = 0; ni < 8; ni++)
                #pragma unroll
                for (int e = 0; e < 4; e++) s[ni][e] = 0.f;

            #pragma unroll
            for (int ks = 0; ks < 4; ks++) {
                #pragma unroll
                for (int p = 0; p < 4; p++) {
                    const uint32_t off = (uint32_t)(p * (16 * TLD * 2) + ks * 32);
                    uint32_t bh[4], bl[4];
                    ldsm4(bh, khi_s + off);
                    ldsm4(bl, klo_s + off);
                    mma16816(s[2*p],   Qh[mi][ks], bh);
                    mma16816(s[2*p],   Qh[mi][ks], bl);
                    mma16816(s[2*p],   Ql[mi][ks], bh);
                    mma16816(s[2*p+1], Qh[mi][ks], bh + 2);
                    mma16816(s[2*p+1], Qh[mi][ks], bl + 2);
                    mma16816(s[2*p+1], Ql[mi][ks], bh + 2);
                }
            }

            // ---- causal mask ----
            if (k0 + 63 > q0 + rbase) {
                const int qa = q0 + rbase + g;
                #pragma unroll
                for (int ni = 0; ni < 8; ni++) {
                    const int kc = k0 + ni * 8 + 2 * t4;
                    if (kc     > qa)     s[ni][0] = -1e30f;
                    if (kc + 1 > qa)     s[ni][1] = -1e30f;
                    if (kc     > qa + 8) s[ni][2] = -1e30f;
                    if (kc + 1 > qa + 8) s[ni][3] = -1e30f;
                }
            }

            // ---- online softmax ----
            float mxA = -1e30f, mxB = -1e30f;
            #pragma unroll
            for (int ni = 0; ni < 8; ni++) {
                mxA = fmaxf(mxA, fmaxf(s[ni][0], s[ni][1]));
                mxB = fmaxf(mxB, fmaxf(s[ni][2], s[ni][3]));
            }
            mxA = fmaxf(mxA, __shfl_xor_sync(0xffffffffu, mxA, 1));
            mxA = fmaxf(mxA, __shfl_xor_sync(0xffffffffu, mxA, 2));
            mxB = fmaxf(mxB, __shfl_xor_sync(0xffffffffu, mxB, 1));
            mxB = fmaxf(mxB, __shfl_xor_sync(0xffffffffu, mxB, 2));

            const float mA = fmaxf(m_[mi][0], mxA);
            const float mB = fmaxf(m_[mi][1], mxB);
            const float scA = __expf(m_[mi][0] - mA);
            const float scB = __expf(m_[mi][1] - mB);
            m_[mi][0] = mA; m_[mi][1] = mB;

            uint32_t Ph[4][4], Pl[4][4];
            float sA = 0.f, sB = 0.f;
            #pragma unroll
            for (int ni = 0; ni < 8; ni++) {
                float p0 = __expf(s[ni][0] - mA);
                float p1 = __expf(s[ni][1] - mA);
                float p2 = __expf(s[ni][2] - mB);
                float p3 = __expf(s[ni][3] - mB);
                sA += p0 + p1; sB += p2 + p3;
                const int ks   = ni >> 1;
                const int base = (ni & 1) * 2;
                split2(p0, p1, Ph[ks][base + 0], Pl[ks][base + 0]);
                split2(p2, p3, Ph[ks][base + 1], Pl[ks][base + 1]);
            }
            sA += __shfl_xor_sync(0xffffffffu, sA, 1);
            sA += __shfl_xor_sync(0xffffffffu, sA, 2);
            sB += __shfl_xor_sync(0xffffffffu, sB, 1);
            sB += __shfl_xor_sync(0xffffffffu, sB, 2);
            l_[mi][0] = l_[mi][0] * scA + sA;
            l_[mi][1] = l_[mi][1] * scB + sB;

            #pragma unroll
            for (int ni = 0; ni < 8; ni++) {
                o[mi][ni][0] *= scA; o[mi][ni][1] *= scA;
                o[mi][ni][2] *= scB; o[mi][ni][3] *= scB;
            }

            // ---- O += P V ----
            #pragma unroll
            for (int ks = 0; ks < 4; ks++) {
                #pragma unroll
                for (int p = 0; p < 4; p++) {
                    const uint32_t off = (uint32_t)(ks * (16 * TLD * 2) + p * 32);
                    uint32_t bh[4], bl[4];
                    ldsm4t(bh, vhi_s + off);
                    ldsm4t(bl, vlo_s + off);
                    mma16816(o[mi][2*p],   Ph[ks], bh);
                    mma16816(o[mi][2*p],   Ph[ks], bl);
                    mma16816(o[mi][2*p],   Pl[ks], bh);
                    mma16816(o[mi][2*p+1], Ph[ks], bh + 2);
                    mma16816(o[mi][2*p+1], Ph[ks], bl + 2);
                    mma16816(o[mi][2*p+1], Pl[ks], bh + 2);
                }
            }
        }
        __syncthreads();
        cur ^= 1;
    }

    // ---- write partials ----
    const size_t pbase = ((size_t)(b * TILES + tile) * NCH_MAX + chunk) * QT;
    #pragma unroll
    for (int mi = 0; mi < 2; mi++) {
        const int lrA = warp * 32 + mi * 16 + g;
        if (t4 == 0) {
            g_pm[pbase + lrA]     = m_[mi][0];
            g_pl[pbase + lrA]     = l_[mi][0];
            g_pm[pbase + lrA + 8] = m_[mi][1];
            g_pl[pbase + lrA + 8] = l_[mi][1];
        }
        #pragma unroll
        for (int ni = 0; ni < 8; ni++) {
            const int c = ni * 8 + 2 * t4;
            float2 vA, vB;
            vA.x = o[mi][ni][0]; vA.y = o[mi][ni][1];
            vB.x = o[mi][ni][2]; vB.y = o[mi][ni][3];
            *(float2*)(g_pacc + (pbase + lrA) * HD + c)       = vA;
            *(float2*)(g_pacc + (pbase + lrA + 8) * HD + c)   = vB;
        }
    }
}

// ---------------------------------------------------------------------------
// Kernel 3: combine split-K partials, float4 vectorized.
// ---------------------------------------------------------------------------
__global__ __launch_bounds__(256) void combine_kernel(float* __restrict__ out)
{
    const int gid = blockIdx.x * 256 + threadIdx.x;
    const int q   = gid >> 4;
    const int d   = (gid & 15) * 4;

    const int b      = q / TT_SEQ;
    const int t_in_b = q % TT_SEQ;
    const int tile   = t_in_b / QT;
    const int qi     = t_in_b % QT;

    const int kmax = (tile + 1) * QT;
    const int nch  = (kmax + CK - 1) / CK;

    const size_t base = ((size_t)(b * TILES + tile) * NCH_MAX) * QT + qi;

    float mstar = -1e30f;
    for (int i = 0; i < nch; i++) {
        float mi = g_pm[base + (size_t)i * QT];
        mstar = fmaxf(mstar, mi);
    }

    float L = 0.f;
    float4 val = make_float4(0.f, 0.f, 0.f, 0.f);
    for (int i = 0; i < nch; i++) {
        const size_t pidx = base + (size_t)i * QT;
        float w = __expf(g_pm[pidx] - mstar);
        L += g_pl[pidx] * w;
        float4 a = *(const float4*)(g_pacc + pidx * HD + d);
        val.x += a.x * w; val.y += a.y * w;
        val.z += a.z * w; val.w += a.w * w;
    }

    const float inv = 1.f / L;
    float4 r;
    r.x = val.x * inv; r.y = val.y * inv; r.z = val.z * inv; r.w = val.w * inv;
    *(float4*)(out + (size_t)q * HD + d) = r;
}

extern "C" void kernel_launch(void* const* d_in, const int* in_sizes, int n_in,
                              void* d_out, int out_size)
{
    const float* x  = (const float*)d_in[0];
    const float* Wq = (const float*)d_in[1];
    const float* Wk = (const float*)d_in[2];
    const float* Wv = (const float*)d_in[3];
    float* out = (float*)d_out;

    cudaFuncSetAttribute(attn_mma, cudaFuncAttributeMaxDynamicSharedMemorySize, ATTN_SMEM);

    convert_w<<<(3 * HD * DD / 4) / 256, 256>>>(Wq, Wk, Wv);
    qkv_hmma<<<(NTOK / GM_BM) * 3, 256>>>(x);

    dim3 agrid(NCH_MAX, TILES, BB);
    attn_mma<<<agrid, 128, ATTN_SMEM>>>();

    combine_kernel<<<(NTOK * 16) / 256, 256>>>(out);
}

// round 10
// speedup vs baseline: 9.1023x; 1.0098x over previous
#include <cuda_runtime.h>
#include <cuda_bf16.h>
#include <math.h>
#include <stdint.h>

#define BB 4
#define TT_SEQ 4096
#define DD 1024
#define HD 64
#define NTOK (BB*TT_SEQ)

#define QT 128
#define CK 512
#define TILES (TT_SEQ/QT)      // 32
#define NCH_MAX (TT_SEQ/CK)    // 8

// Q/K/V stored ONLY as packed bf16 hi/lo (pair-packed uint32 at even cols).
// Q pre-scaled by hd^-0.5.
__device__ __nv_bfloat16 g_Qhi[NTOK*HD];
__device__ __nv_bfloat16 g_Qlo[NTOK*HD];
__device__ __nv_bfloat16 g_Khi[NTOK*HD];
__device__ __nv_bfloat16 g_Klo[NTOK*HD];
__device__ __nv_bfloat16 g_Vhi[NTOK*HD];
__device__ __nv_bfloat16 g_Vlo[NTOK*HD];

// Split-K partials
__device__ float g_pacc[BB*TILES*NCH_MAX*QT*HD];
__device__ float g_pm  [BB*TILES*NCH_MAX*QT];
__device__ float g_pl  [BB*TILES*NCH_MAX*QT];

__device__ __forceinline__ uint32_t pack_bf16(float a, float b) {
    __nv_bfloat162 t = __floats2bfloat162_rn(a, b);
    return *reinterpret_cast<uint32_t*>(&t);
}

__device__ __forceinline__ void split2(float a, float b, uint32_t& hi, uint32_t& lo) {
    __nv_bfloat162 h = __floats2bfloat162_rn(a, b);
    hi = *reinterpret_cast<uint32_t*>(&h);
    lo = pack_bf16(a - __bfloat162float(h.x), b - __bfloat162float(h.y));
}

__device__ __forceinline__ void mma16816(float* d, const uint32_t* a, const uint32_t* b) {
    asm volatile(
        "mma.sync.aligned.m16n8k16.row.col.f32.bf16.bf16.f32 "
        "{%0,%1,%2,%3}, {%4,%5,%6,%7}, {%8,%9}, {%0,%1,%2,%3};"
        : "+f"(d[0]), "+f"(d[1]), "+f"(d[2]), "+f"(d[3])
        : "r"(a[0]), "r"(a[1]), "r"(a[2]), "r"(a[3]),
          "r"(b[0]), "r"(b[1]));
}

__device__ __forceinline__ void ldsm4(uint32_t* d, uint32_t addr) {
    asm volatile("ldmatrix.sync.aligned.m8n8.x4.shared.b16 {%0,%1,%2,%3}, [%4];"
        : "=r"(d[0]), "=r"(d[1]), "=r"(d[2]), "=r"(d[3]) : "r"(addr));
}
__device__ __forceinline__ void ldsm4t(uint32_t* d, uint32_t addr) {
    asm volatile("ldmatrix.sync.aligned.m8n8.x4.trans.shared.b16 {%0,%1,%2,%3}, [%4];"
        : "=r"(d[0]), "=r"(d[1]), "=r"(d[2]), "=r"(d[3]) : "r"(addr));
}

#define CP_ASYNC16(saddr, gptr) \
    asm volatile("cp.async.cg.shared.global [%0], [%1], 16;" :: "r"(saddr), "l"(gptr) : "memory")
#define CP_COMMIT() asm volatile("cp.async.commit_group;" ::: "memory")
#define CP_WAIT0()  asm volatile("cp.async.wait_group 0;" ::: "memory")

// ---------------------------------------------------------------------------
// Kernel 1: QKV projection via mma.sync + ldmatrix fragment loads.
// W converted fp32 -> bf16 hi/lo in-kernel (convert_w fused away).
// ---------------------------------------------------------------------------
#define GM_BM 128
#define GM_BN 64
#define GM_BK 32
#define XLD 40
#define WLD 40

__global__ __launch_bounds__(256) void qkv_hmma(
    const float* __restrict__ x,
    const float* __restrict__ Wq,
    const float* __restrict__ Wk,
    const float* __restrict__ Wv)
{
    __shared__ __nv_bfloat16 xhi[GM_BM * XLD];
    __shared__ __nv_bfloat16 xlo[GM_BM * XLD];
    __shared__ __nv_bfloat16 whi[GM_BN * WLD];
    __shared__ __nv_bfloat16 wlo[GM_BN * WLD];

    const int nblk = blockIdx.x % 3;
    const int m0   = (blockIdx.x / 3) * GM_BM;
    const float* W = (nblk == 0) ? Wq : (nblk == 1) ? Wk : Wv;
    const float wscale = (nblk == 0) ? 0.125f : 1.0f;

    const int tid  = threadIdx.x;
    const int warp = tid >> 5;
    const int lane = tid & 31;
    const int wm   = (warp & 3) * 32;
    const int wn   = (warp >> 2) * 32;
    const int g    = lane >> 2;
    const int t4   = lane & 3;

    const int la = lane >> 3;
    const int lr = lane & 7;
    const uint32_t a_off = (uint32_t)((((la & 1) * 8 + lr) * XLD + (la >> 1) * 8) * 2);
    const uint32_t b_off = (uint32_t)((((la >> 1) * 8 + lr) * WLD + (la & 1) * 8) * 2);

    const uint32_t xhi_s = (uint32_t)__cvta_generic_to_shared(xhi) + (uint32_t)(wm * XLD * 2) + a_off;
    const uint32_t xlo_s = (uint32_t)__cvta_generic_to_shared(xlo) + (uint32_t)(wm * XLD * 2) + a_off;
    const uint32_t whi_s = (uint32_t)__cvta_generic_to_shared(whi) + (uint32_t)(wn * WLD * 2) + b_off;
    const uint32_t wlo_s = (uint32_t)__cvta_generic_to_shared(wlo) + (uint32_t)(wn * WLD * 2) + b_off;

    float acc[2][4][4];
    #pragma unroll
    for (int mi = 0; mi < 2; mi++)
        #pragma unroll
        for (int ni = 0; ni < 4; ni++)
            #pragma unroll
            for (int k = 0; k < 4; k++) acc[mi][ni][k] = 0.f;

    const int xr = tid >> 1;
    const int xp = tid & 1;
    const int wr = tid >> 2;           // W row 0..63
    const int wc = (tid & 3) * 8;      // W col group of 8 floats

    for (int k0 = 0; k0 < DD; k0 += GM_BK) {
        __syncthreads();
        {   // X: 128x32 fp32 -> bf16 hi/lo
            const float4* src = (const float4*)(x + (size_t)(m0 + xr) * DD + k0 + xp * 16);
            #pragma unroll
            for (int i = 0; i < 4; i++) {
                float4 v = src[i];
                const int o = xr * XLD + xp * 16 + i * 4;
                uint32_t h0, l0, h1, l1;
                split2(v.x, v.y, h0, l0);
                split2(v.z, v.w, h1, l1);
                *(uint32_t*)(xhi + o + 0) = h0;
                *(uint32_t*)(xhi + o + 2) = h1;
                *(uint32_t*)(xlo + o + 0) = l0;
                *(uint32_t*)(xlo + o + 2) = l1;
            }
        }
        {   // W: 64x32 fp32 -> bf16 hi/lo (in-kernel, Q-scale folded)
            const float4* src = (const float4*)(W + (size_t)wr * DD + k0 + wc);
            #pragma unroll
            for (int i = 0; i < 2; i++) {
                float4 v = src[i];
                v.x *= wscale; v.y *= wscale; v.z *= wscale; v.w *= wscale;
                const int o = wr * WLD + wc + i * 4;
                uint32_t h0, l0, h1, l1;
                split2(v.x, v.y, h0, l0);
                split2(v.z, v.w, h1, l1);
                *(uint32_t*)(whi + o + 0) = h0;
                *(uint32_t*)(whi + o + 2) = h1;
                *(uint32_t*)(wlo + o + 0) = l0;
                *(uint32_t*)(wlo + o + 2) = l1;
            }
        }
        __syncthreads();

        #pragma unroll
        for (int kk = 0; kk < GM_BK; kk += 16) {
            uint32_t ah[2][4], al[2][4], bh[2][4], bl[2][4];
            const uint32_t ko = (uint32_t)(kk * 2);
            ldsm4(ah[0], xhi_s + ko);
            ldsm4(ah[1], xhi_s + (uint32_t)(16 * XLD * 2) + ko);
            ldsm4(al[0], xlo_s + ko);
            ldsm4(al[1], xlo_s + (uint32_t)(16 * XLD * 2) + ko);
            ldsm4(bh[0], whi_s + ko);
            ldsm4(bh[1], whi_s + (uint32_t)(16 * WLD * 2) + ko);
            ldsm4(bl[0], wlo_s + ko);
            ldsm4(bl[1], wlo_s + (uint32_t)(16 * WLD * 2) + ko);

            #pragma unroll
            for (int mi = 0; mi < 2; mi++) {
                #pragma unroll
                for (int nj = 0; nj < 2; nj++) {
                    mma16816(acc[mi][2*nj],   ah[mi], bh[nj]);
                    mma16816(acc[mi][2*nj+1], ah[mi], bh[nj] + 2);
                    mma16816(acc[mi][2*nj],   ah[mi], bl[nj]);
                    mma16816(acc[mi][2*nj+1], ah[mi], bl[nj] + 2);
                    mma16816(acc[mi][2*nj],   al[mi], bh[nj]);
                    mma16816(acc[mi][2*nj+1], al[mi], bh[nj] + 2);
                }
            }
        }
    }

    __nv_bfloat16* dhi = (nblk == 0) ? g_Qhi : (nblk == 1) ? g_Khi : g_Vhi;
    __nv_bfloat16* dlo = (nblk == 0) ? g_Qlo : (nblk == 1) ? g_Klo : g_Vlo;
    #pragma unroll
    for (int mi = 0; mi < 2; mi++) {
        #pragma unroll
        for (int ni = 0; ni < 4; ni++) {
            const size_t r0 = (size_t)m0 + wm + mi * 16 + g;
            const int    c  = wn + ni * 8 + 2 * t4;
            uint32_t h, l;
            split2(acc[mi][ni][0], acc[mi][ni][1], h, l);
            *(uint32_t*)(dhi + r0 * HD + c) = h;
            *(uint32_t*)(dlo + r0 * HD + c) = l;
            split2(acc[mi][ni][2], acc[mi][ni][3], h, l);
            *(uint32_t*)(dhi + (r0 + 8) * HD + c) = h;
            *(uint32_t*)(dlo + (r0 + 8) * HD + c) = l;
        }
    }
}

// ---------------------------------------------------------------------------
// Kernel 2: split-K causal flash attention, cp.async double-buffered. CK=512.
// ---------------------------------------------------------------------------
#define TLD 72
#define ARR_B  (64 * TLD * 2)      // 9216 bytes per array
#define BUF_B  (4 * ARR_B)         // 36864 bytes per buffer
#define ATTN_SMEM (2 * BUF_B)      // 73728

__global__ __launch_bounds__(128) void attn_mma()
{
    extern __shared__ char dsm[];

    const int chunk = blockIdx.x;
    const int tile  = blockIdx.y;
    const int b     = blockIdx.z;

    const int kmax = (tile + 1) * QT;
    const int nch  = (kmax + CK - 1) / CK;
    if (chunk >= nch) return;

    const int kstart = chunk * CK;
    const int kend   = min(kstart + CK, kmax);
    const int q0     = tile * QT;

    const int tid  = threadIdx.x;
    const int warp = tid >> 5;
    const int lane = tid & 31;
    const int g    = lane >> 2;
    const int t4   = lane & 3;

    const size_t boff = (size_t)b * TT_SEQ * HD;
    const uint32_t sb = (uint32_t)__cvta_generic_to_shared(dsm);

    const int la = lane >> 3;
    const int lr = lane & 7;
    const uint32_t k_lane_off = (uint32_t)((((la >> 1) * 8 + lr) * TLD + (la & 1) * 8) * 2);
    const uint32_t v_lane_off = (uint32_t)((((la & 1) * 8 + lr) * TLD + (la >> 1) * 8) * 2);

    // ---- Q fragments: direct packed-pair loads ----
    uint32_t Qh[2][4][4], Ql[2][4][4];
    #pragma unroll
    for (int mi = 0; mi < 2; mi++) {
        const size_t ar = boff + (size_t)(q0 + warp * 32 + mi * 16 + g) * HD;
        #pragma unroll
        for (int ks = 0; ks < 4; ks++) {
            const int c = ks * 16 + 2 * t4;
            Qh[mi][ks][0] = *(const uint32_t*)(g_Qhi + ar + c);
            Qh[mi][ks][1] = *(const uint32_t*)(g_Qhi + ar + 8 * HD + c);
            Qh[mi][ks][2] = *(const uint32_t*)(g_Qhi + ar + c + 8);
            Qh[mi][ks][3] = *(const uint32_t*)(g_Qhi + ar + 8 * HD + c + 8);
            Ql[mi][ks][0] = *(const uint32_t*)(g_Qlo + ar + c);
            Ql[mi][ks][1] = *(const uint32_t*)(g_Qlo + ar + 8 * HD + c);
            Ql[mi][ks][2] = *(const uint32_t*)(g_Qlo + ar + c + 8);
            Ql[mi][ks][3] = *(const uint32_t*)(g_Qlo + ar + 8 * HD + c + 8);
        }
    }

    float o[2][8][4];
    #pragma unroll
    for (int mi = 0; mi < 2; mi++)
        #pragma unroll
        for (int ni = 0; ni < 8; ni++)
            #pragma unroll
            for (int e = 0; e < 4; e++) o[mi][ni][e] = 0.f;
    float m_[2][2] = {{-1e20f, -1e20f}, {-1e20f, -1e20f}};
    float l_[2][2] = {{0.f, 0.f}, {0.f, 0.f}};

    auto stage_tile = [&](uint32_t sbase, int k0) {
        #pragma unroll
        for (int i = 0; i < 4; i++) {
            const int idx = i * 128 + tid;
            const int row = idx >> 3;
            const int seg = (idx & 7) * 8;
            const size_t gsrc = boff + (size_t)(k0 + row) * HD + seg;
            const uint32_t sdst = sbase + (uint32_t)((row * TLD + seg) * 2);
            CP_ASYNC16(sdst + 0 * ARR_B, g_Khi + gsrc);
            CP_ASYNC16(sdst + 1 * ARR_B, g_Klo + gsrc);
            CP_ASYNC16(sdst + 2 * ARR_B, g_Vhi + gsrc);
            CP_ASYNC16(sdst + 3 * ARR_B, g_Vlo + gsrc);
        }
    };

    stage_tile(sb, kstart);
    CP_COMMIT();

    int cur = 0;
    for (int k0 = kstart; k0 < kend; k0 += 64) {
        CP_WAIT0();
        __syncthreads();
        if (k0 + 64 < kend) {
            stage_tile(sb + (uint32_t)((cur ^ 1) * BUF_B), k0 + 64);
            CP_COMMIT();
        }

        const uint32_t bufb  = sb + (uint32_t)(cur * BUF_B);
        const uint32_t khi_s = bufb + 0 * ARR_B + k_lane_off;
        const uint32_t klo_s = bufb + 1 * ARR_B + k_lane_off;
        const uint32_t vhi_s = bufb + 2 * ARR_B + v_lane_off;
        const uint32_t vlo_s = bufb + 3 * ARR_B + v_lane_off;

        #pragma unroll
        for (int mi = 0; mi < 2; mi++) {
            const int rbase = warp * 32 + mi * 16;

            // ---- S = Q K^T ----
            float s[8][4];
            #pragma unroll
            for (int ni = 0; ni < 8; ni++)
                #pragma unroll
                for (int e = 0; e < 4; e++) s[ni][e] = 0.f;

            #pragma unroll
            for (int ks = 0; ks < 4; ks++) {
                #pragma unroll
                for (int p = 0; p < 4; p++) {
                    const uint32_t off = (uint32_t)(p * (16 * TLD * 2) + ks * 32);
                    uint32_t bh[4], bl[4];
                    ldsm4(bh, khi_s + off);
                    ldsm4(bl, klo_s + off);
                    mma16816(s[2*p],   Qh[mi][ks], bh);
                    mma16816(s[2*p],   Qh[mi][ks], bl);
                    mma16816(s[2*p],   Ql[mi][ks], bh);
                    mma16816(s[2*p+1], Qh[mi][ks], bh + 2);
                    mma16816(s[2*p+1], Qh[mi][ks], bl + 2);
                    mma16816(s[2*p+1], Ql[mi][ks], bh + 2);
                }
            }

            // ---- causal mask ----
            if (k0 + 63 > q0 + rbase) {
                const int qa = q0 + rbase + g;
                #pragma unroll
                for (int ni = 0; ni < 8; ni++) {
                    const int kc = k0 + ni * 8 + 2 * t4;
                    if (kc     > qa)     s[ni][0] = -1e30f;
                    if (kc + 1 > qa)     s[ni][1] = -1e30f;
                    if (kc     > qa + 8) s[ni][2] = -1e30f;
                    if (kc + 1 > qa + 8) s[ni][3] = -1e30f;
                }
            }

            // ---- online softmax ----
            float mxA = -1e30f, mxB = -1e30f;
            #pragma unroll
            for (int ni = 0; ni < 8; ni++) {
                mxA = fmaxf(mxA, fmaxf(s[ni][0], s[ni][1]));
                mxB = fmaxf(mxB, fmaxf(s[ni][2], s[ni][3]));
            }
            mxA = fmaxf(mxA, __shfl_xor_sync(0xffffffffu, mxA, 1));
            mxA = fmaxf(mxA, __shfl_xor_sync(0xffffffffu, mxA, 2));
            mxB = fmaxf(mxB, __shfl_xor_sync(0xffffffffu, mxB, 1));
            mxB = fmaxf(mxB, __shfl_xor_sync(0xffffffffu, mxB, 2));

            const float mA = fmaxf(m_[mi][0], mxA);
            const float mB = fmaxf(m_[mi][1], mxB);
            const float scA = __expf(m_[mi][0] - mA);
            const float scB = __expf(m_[mi][1] - mB);
            m_[mi][0] = mA; m_[mi][1] = mB;

            uint32_t Ph[4][4], Pl[4][4];
            float sA = 0.f, sB = 0.f;
            #pragma unroll
            for (int ni = 0; ni < 8; ni++) {
                float p0 = __expf(s[ni][0] - mA);
                float p1 = __expf(s[ni][1] - mA);
                float p2 = __expf(s[ni][2] - mB);
                float p3 = __expf(s[ni][3] - mB);
                sA += p0 + p1; sB += p2 + p3;
                const int ks   = ni >> 1;
                const int base = (ni & 1) * 2;
                split2(p0, p1, Ph[ks][base + 0], Pl[ks][base + 0]);
                split2(p2, p3, Ph[ks][base + 1], Pl[ks][base + 1]);
            }
            sA += __shfl_xor_sync(0xffffffffu, sA, 1);
            sA += __shfl_xor_sync(0xffffffffu, sA, 2);
            sB += __shfl_xor_sync(0xffffffffu, sB, 1);
            sB += __shfl_xor_sync(0xffffffffu, sB, 2);
            l_[mi][0] = l_[mi][0] * scA + sA;
            l_[mi][1] = l_[mi][1] * scB + sB;

            #pragma unroll
            for (int ni = 0; ni < 8; ni++) {
                o[mi][ni][0] *= scA; o[mi][ni][1] *= scA;
                o[mi][ni][2] *= scB; o[mi][ni][3] *= scB;
            }

            // ---- O += P V ----
            #pragma unroll
            for (int ks = 0; ks < 4; ks++) {
                #pragma unroll
                for (int p = 0; p < 4; p++) {
                    const uint32_t off = (uint32_t)(ks * (16 * TLD * 2) + p * 32);
                    uint32_t bh[4], bl[4];
                    ldsm4t(bh, vhi_s + off);
                    ldsm4t(bl, vlo_s + off);
                    mma16816(o[mi][2*p],   Ph[ks], bh);
                    mma16816(o[mi][2*p],   Ph[ks], bl);
                    mma16816(o[mi][2*p],   Pl[ks], bh);
                    mma16816(o[mi][2*p+1], Ph[ks], bh + 2);
                    mma16816(o[mi][2*p+1], Ph[ks], bl + 2);
                    mma16816(o[mi][2*p+1], Pl[ks], bh + 2);
                }
            }
        }
        __syncthreads();
        cur ^= 1;
    }

    // ---- write partials ----
    const size_t pbase = ((size_t)(b * TILES + tile) * NCH_MAX + chunk) * QT;
    #pragma unroll
    for (int mi = 0; mi < 2; mi++) {
        const int lrA = warp * 32 + mi * 16 + g;
        if (t4 == 0) {
            g_pm[pbase + lrA]     = m_[mi][0];
            g_pl[pbase + lrA]     = l_[mi][0];
            g_pm[pbase + lrA + 8] = m_[mi][1];
            g_pl[pbase + lrA + 8] = l_[mi][1];
        }
        #pragma unroll
        for (int ni = 0; ni < 8; ni++) {
            const int c = ni * 8 + 2 * t4;
            float2 vA, vB;
            vA.x = o[mi][ni][0]; vA.y = o[mi][ni][1];
            vB.x = o[mi][ni][2]; vB.y = o[mi][ni][3];
            *(float2*)(g_pacc + (pbase + lrA) * HD + c)       = vA;
            *(float2*)(g_pacc + (pbase + lrA + 8) * HD + c)   = vB;
        }
    }
}

// ---------------------------------------------------------------------------
// Kernel 3: combine split-K partials, float4 vectorized.
// ---------------------------------------------------------------------------
__global__ __launch_bounds__(256) void combine_kernel(float* __restrict__ out)
{
    const int gid = blockIdx.x * 256 + threadIdx.x;
    const int q   = gid >> 4;
    const int d   = (gid & 15) * 4;

    const int b      = q / TT_SEQ;
    const int t_in_b = q % TT_SEQ;
    const int tile   = t_in_b / QT;
    const int qi     = t_in_b % QT;

    const int kmax = (tile + 1) * QT;
    const int nch  = (kmax + CK - 1) / CK;

    const size_t base = ((size_t)(b * TILES + tile) * NCH_MAX) * QT + qi;

    float mstar = -1e30f;
    for (int i = 0; i < nch; i++) {
        float mi = g_pm[base + (size_t)i * QT];
        mstar = fmaxf(mstar, mi);
    }

    float L = 0.f;
    float4 val = make_float4(0.f, 0.f, 0.f, 0.f);
    for (int i = 0; i < nch; i++) {
        const size_t pidx = base + (size_t)i * QT;
        float w = __expf(g_pm[pidx] - mstar);
        L += g_pl[pidx] * w;
        float4 a = *(const float4*)(g_pacc + pidx * HD + d);
        val.x += a.x * w; val.y += a.y * w;
        val.z += a.z * w; val.w += a.w * w;
    }

    const float inv = 1.f / L;
    float4 r;
    r.x = val.x * inv; r.y = val.y * inv; r.z = val.z * inv; r.w = val.w * inv;
    *(float4*)(out + (size_t)q * HD + d) = r;
}

extern "C" void kernel_launch(void* const* d_in, const int* in_sizes, int n_in,
                              void* d_out, int out_size)
{
    const float* x  = (const float*)d_in[0];
    const float* Wq = (const float*)d_in[1];
    const float* Wk = (const float*)d_in[2];
    const float* Wv = (const float*)d_in[3];
    float* out = (float*)d_out;

    cudaFuncSetAttribute(attn_mma, cudaFuncAttributeMaxDynamicSharedMemorySize, ATTN_SMEM);

    qkv_hmma<<<(NTOK / GM_BM) * 3, 256>>>(x, Wq, Wk, Wv);

    dim3 agrid(NCH_MAX, TILES, BB);
    attn_mma<<<agrid, 128, ATTN_SMEM>>>();

    combine_kernel<<<(NTOK * 16) / 256, 256>>>(out);
}